// round 5
// baseline (speedup 1.0000x reference)
#include <cuda_runtime.h>
#include <stdint.h>

// ---------------------------------------------------------------------------
// MagnitudePruning via sampled-window radix select on s = t*magnitude + |x|
// (monotone surrogate: division by uniform (t+1) preserves rank).
//
// zero     : clear small histograms/counters (single block)
// sample   : ~1M strided samples -> 4096-bin hist -> window [b_lo,b_hi]
// passA    : ONE full fused pass: exact below-count, write out for
//            out-of-window elems, compact in-window candidates to
//            per-block regions, shared window histogram
// candfilt : select b1/r1; finalize non-b1 candidates; compact b1-cands
//            to g_cand2; 1024-bin mid-bit histogram
// selmid   : (1 block) select mid bin b2; low-bit hist of cand2; exact thr
// finalize2: rewrite kept b1-candidates (or exact single-block fallback)
// ---------------------------------------------------------------------------

#define SAMP_BINS  4096u          // top 12 bits
#define WBINS      1024u          // window width cap (bins)
#define NBLOCKS    1184u
#define NTHREADS   256u
#define TILE_F4    512u           // float4s per tile (2048 elements)
#define TILE_ELEM  2048u
#define PER_BLOCK  40960u         // candidate region capacity per block
#define CAND2_MAX  (1u << 22)     // b1-candidate list capacity (4M)

__device__ unsigned g_samp_hist[SAMP_BINS];
__device__ unsigned g_whist[WBINS];
__device__ unsigned g_hist_mid[1024];
__device__ unsigned g_below;
__device__ unsigned g_done;
__device__ unsigned g_ovf;
__device__ unsigned g_fb;
__device__ unsigned g_blo, g_bhi;
__device__ unsigned g_b1, g_r1, g_thr_key;
__device__ unsigned g_ncand2;
__device__ unsigned g_blk_cnt[NBLOCKS];
__device__ uint2    g_cand[NBLOCKS * PER_BLOCK];
__device__ uint2    g_cand2[CAND2_MAX];

__device__ __forceinline__ unsigned key_of(float x, float m, float tf) {
    float s = __fadd_rn(__fmul_rn(tf, m), fabsf(x));
    return __float_as_uint(s);
}
__device__ __forceinline__ float read_tf(const int* t_ptr) {
    return t_ptr ? (float)(*t_ptr) : 1.0f;
}
__device__ __forceinline__ unsigned rank_R(const float* sp, unsigned n) {
    float fidx = floorf(__fsub_rn(__fmul_rn(sp[0], (float)n), 1.0f));
    long long idx = (long long)fidx;
    if (idx < 0) idx = 0;
    if (idx > (long long)(n - 1)) idx = (long long)(n - 1);
    return (unsigned)idx + 1u;
}
__device__ __forceinline__ void agg_shared_add(unsigned* hist, unsigned bin) {
    unsigned act    = __activemask();
    unsigned peers  = __match_any_sync(act, bin);
    int      leader = __ffs(peers) - 1;
    if ((int)(threadIdx.x & 31) == leader)
        atomicAdd(&hist[bin], (unsigned)__popc(peers));
}

// ---------------------------------------------------------------------------
__global__ void zero_kernel() {
    unsigned tid = threadIdx.x;
    for (unsigned i = tid; i < SAMP_BINS; i += blockDim.x) g_samp_hist[i] = 0u;
    for (unsigned i = tid; i < WBINS;     i += blockDim.x) g_whist[i] = 0u;
    for (unsigned i = tid; i < 1024u;     i += blockDim.x) g_hist_mid[i] = 0u;
    if (tid == 0) {
        g_below = 0u; g_done = 0u; g_ovf = 0u; g_fb = 0u; g_ncand2 = 0u;
    }
}

// ---------------------------------------------------------------------------
// Sample ~1M elements (256K float4s evenly strided), 4096-bin hist; the last
// block to finish computes the window [b_lo, b_hi] (rank margin +-1%).
__global__ void sample_kernel(const float* __restrict__ xs,
                              const float* __restrict__ ms,
                              const int* __restrict__ t_ptr,
                              const float* __restrict__ sparsity,
                              unsigned n) {
    __shared__ unsigned sh[SAMP_BINS];
    for (unsigned i = threadIdx.x; i < SAMP_BINS; i += blockDim.x) sh[i] = 0u;
    __syncthreads();

    float tf = read_tf(t_ptr);
    unsigned n4 = n >> 2;
    unsigned stride4 = n4 / 262144u; if (stride4 == 0u) stride4 = 1u;
    unsigned nsamp4  = n4 / stride4;
    const float4* x4 = (const float4*)xs;
    const float4* m4 = (const float4*)ms;

    unsigned gstride = gridDim.x * blockDim.x;
    for (unsigned i = blockIdx.x * blockDim.x + threadIdx.x; i < nsamp4; i += gstride) {
        unsigned idx = i * stride4;
        float4 xv = x4[idx];
        float4 mv = m4[idx];
        agg_shared_add(sh, key_of(xv.x, mv.x, tf) >> 20);
        agg_shared_add(sh, key_of(xv.y, mv.y, tf) >> 20);
        agg_shared_add(sh, key_of(xv.z, mv.z, tf) >> 20);
        agg_shared_add(sh, key_of(xv.w, mv.w, tf) >> 20);
    }
    __syncthreads();
    for (unsigned i = threadIdx.x; i < SAMP_BINS; i += blockDim.x) {
        unsigned c = sh[i];
        if (c) atomicAdd(&g_samp_hist[i], c);
    }
    __threadfence();

    __shared__ unsigned slast;
    if (threadIdx.x == 0)
        slast = (atomicAdd(&g_done, 1u) == gridDim.x - 1u) ? 1u : 0u;
    __syncthreads();
    if (!slast) return;

    // ---- last block: compute window ----
    __shared__ unsigned sscan[256];
    __shared__ unsigned svlo, svhi;
    int t = threadIdx.x;               // 256 threads, 16 bins each
    unsigned loc[16];
    unsigned lsum = 0u;
    #pragma unroll
    for (int j = 0; j < 16; j++) { loc[j] = g_samp_hist[t * 16 + j]; lsum += loc[j]; }
    sscan[t] = lsum;
    __syncthreads();
    for (int off = 1; off < 256; off <<= 1) {
        unsigned v = (t >= off) ? sscan[t - off] : 0u;
        __syncthreads();
        sscan[t] += v;
        __syncthreads();
    }
    unsigned incl  = sscan[t];
    unsigned total = sscan[255];
    unsigned before = incl - lsum;

    unsigned R = rank_R(sparsity, n);
    float f = (float)R / (float)n;
    float tlo = (f - 0.01f) * (float)total;
    float thi = (f + 0.01f) * (float)total + 1.0f;
    unsigned slo = (tlo < 1.0f) ? 1u : (unsigned)tlo;
    if (slo > total) slo = total;
    unsigned shi = (thi < 1.0f) ? 1u : (unsigned)thi;
    if (shi > total) shi = total;
    if (shi < slo) shi = slo;

    if (slo > before && slo <= incl) {
        unsigned run = before;
        #pragma unroll
        for (int j = 0; j < 16; j++) {
            if (slo <= run + loc[j]) { svlo = (unsigned)(t * 16 + j); break; }
            run += loc[j];
        }
    }
    if (shi > before && shi <= incl) {
        unsigned run = before;
        #pragma unroll
        for (int j = 0; j < 16; j++) {
            if (shi <= run + loc[j]) { svhi = (unsigned)(t * 16 + j); break; }
            run += loc[j];
        }
    }
    __syncthreads();
    if (t == 0) {
        unsigned blo = svlo, bhi = svhi;
        if (bhi < blo) bhi = blo;
        if (bhi - blo + 1u > WBINS) bhi = blo + WBINS - 1u;
        g_blo = blo; g_bhi = bhi;
    }
}

// ---------------------------------------------------------------------------
// The single fused full pass.
__global__ void passA_kernel(const float* __restrict__ xs,
                             const float* __restrict__ ms,
                             const int* __restrict__ t_ptr,
                             float* __restrict__ out,
                             unsigned n) {
    __shared__ uint2    s_buf[TILE_ELEM];
    __shared__ unsigned s_whist[WBINS];
    __shared__ unsigned s_cnt;
    __shared__ unsigned s_red[NTHREADS];

    for (unsigned i = threadIdx.x; i < WBINS; i += blockDim.x) s_whist[i] = 0u;

    float tf = read_tf(t_ptr);
    unsigned b_lo = g_blo, b_hi = g_bhi;
    unsigned n4 = n >> 2;
    const float4* x4 = (const float4*)xs;
    const float4* m4 = (const float4*)ms;
    float4* o4 = (float4*)out;

    unsigned region = blockIdx.x * PER_BLOCK;
    unsigned nreg = 0u;
    unsigned below = 0u;
    unsigned ntiles = (n4 + TILE_F4 - 1u) / TILE_F4;

    for (unsigned tile = blockIdx.x; tile < ntiles; tile += gridDim.x) {
        if (threadIdx.x == 0) s_cnt = 0u;
        __syncthreads();

        unsigned tbase = tile * TILE_F4;
        #pragma unroll
        for (int k = 0; k < 2; k++) {
            unsigned i = tbase + (unsigned)k * NTHREADS + threadIdx.x;
            if (i < n4) {
                float4 xv = x4[i];
                float4 mv = m4[i];
                unsigned e = i * 4u;
                unsigned kk[4];
                kk[0] = key_of(xv.x, mv.x, tf);
                kk[1] = key_of(xv.y, mv.y, tf);
                kk[2] = key_of(xv.z, mv.z, tf);
                kk[3] = key_of(xv.w, mv.w, tf);
                float vv[4] = {xv.x, xv.y, xv.z, xv.w};
                float ov[4];
                #pragma unroll
                for (int j = 0; j < 4; j++) {
                    unsigned top = kk[j] >> 20;
                    below += (top < b_lo) ? 1u : 0u;
                    ov[j] = (top > b_hi) ? vv[j] : 0.0f;
                    if (top >= b_lo && top <= b_hi) {
                        unsigned pos = atomicAdd(&s_cnt, 1u);
                        s_buf[pos] = make_uint2(kk[j], e + (unsigned)j);
                        agg_shared_add(s_whist, top - b_lo);
                    }
                }
                o4[i] = make_float4(ov[0], ov[1], ov[2], ov[3]);
            }
        }
        __syncthreads();

        unsigned cnt = s_cnt;
        if (cnt) {
            if (nreg + cnt <= PER_BLOCK) {
                for (unsigned j = threadIdx.x; j < cnt; j += blockDim.x)
                    g_cand[region + nreg + j] = s_buf[j];
                nreg += cnt;
            } else {
                if (threadIdx.x == 0) atomicExch(&g_ovf, 1u);
            }
        }
        __syncthreads();
    }

    // scalar tail (n % 4)
    if (blockIdx.x == 0 && threadIdx.x == 0) {
        for (unsigned i = n4 << 2; i < n; i++) {
            unsigned k = key_of(xs[i], ms[i], tf);
            unsigned top = k >> 20;
            below += (top < b_lo) ? 1u : 0u;
            out[i] = (top > b_hi) ? xs[i] : 0.0f;
            if (top >= b_lo && top <= b_hi) {
                if (nreg < PER_BLOCK) {
                    g_cand[region + nreg] = make_uint2(k, i);
                    nreg++;
                    atomicAdd(&s_whist[top - b_lo], 1u);
                } else {
                    atomicExch(&g_ovf, 1u);
                }
            }
        }
    }
    __syncthreads();

    if (threadIdx.x == 0) g_blk_cnt[blockIdx.x] = nreg;

    s_red[threadIdx.x] = below;
    __syncthreads();
    for (int off = NTHREADS / 2; off > 0; off >>= 1) {
        if ((int)threadIdx.x < off) s_red[threadIdx.x] += s_red[threadIdx.x + off];
        __syncthreads();
    }
    if (threadIdx.x == 0 && s_red[0]) atomicAdd(&g_below, s_red[0]);

    for (unsigned i = threadIdx.x; i < WBINS; i += blockDim.x) {
        unsigned c = s_whist[i];
        if (c) atomicAdd(&g_whist[i], c);
    }
}

// ---------------------------------------------------------------------------
// Select b1/r1; finalize non-b1 candidates in own region; compact b1-cands
// into g_cand2; build 1024-bin mid-bit [10,20) histogram of b1-cands.
__global__ void candfilter_kernel(const float* __restrict__ xs,
                                  const float* __restrict__ sparsity,
                                  float* __restrict__ out,
                                  unsigned n) {
    __shared__ unsigned ss[NTHREADS];
    __shared__ unsigned sb1, sr1;
    __shared__ unsigned s_hmid[1024];
    __shared__ unsigned s_base;
    int t = threadIdx.x;
    if (t == 0) { sb1 = 0xFFFFFFFFu; sr1 = 1u; }
    for (unsigned i = t; i < 1024u; i += blockDim.x) s_hmid[i] = 0u;

    unsigned c[4];
    unsigned local = 0u;
    #pragma unroll
    for (int j = 0; j < 4; j++) { c[j] = g_whist[t * 4 + j]; local += c[j]; }
    ss[t] = local;
    __syncthreads();
    for (int off = 1; off < NTHREADS; off <<= 1) {
        unsigned v = (t >= off) ? ss[t - off] : 0u;
        __syncthreads();
        ss[t] += v;
        __syncthreads();
    }
    unsigned incl   = ss[t];
    unsigned total  = ss[NTHREADS - 1];
    unsigned before = incl - local;

    unsigned below = g_below;
    unsigned R = rank_R(sparsity, n);
    bool fb = (below >= R) || ((R - below) > total) || (g_ovf != 0u);
    unsigned Rp = R - below;

    if (!fb && Rp > before && Rp <= incl) {
        unsigned run = before;
        #pragma unroll
        for (int j = 0; j < 4; j++) {
            if (Rp <= run + c[j]) {
                sb1 = g_blo + (unsigned)(t * 4 + j);
                sr1 = Rp - run;
                break;
            }
            run += c[j];
        }
    }
    __syncthreads();

    if (blockIdx.x == 0 && t == 0) {
        g_fb = fb ? 1u : 0u;
        if (!fb) { g_b1 = sb1; g_r1 = sr1; }
    }
    if (fb) return;

    unsigned b1     = sb1;
    unsigned cnt    = g_blk_cnt[blockIdx.x];
    unsigned region = blockIdx.x * PER_BLOCK;

    // phase 1: finalize non-b1 candidates; count own b1-cands per thread
    unsigned myb1 = 0u;
    for (unsigned j = (unsigned)t; j < cnt; j += blockDim.x) {
        uint2 r = g_cand[region + j];
        unsigned top = r.x >> 20;
        if (top > b1)       out[r.y] = xs[r.y];
        else if (top == b1) myb1++;
    }

    // prefix over per-thread counts -> block total -> global base
    ss[t] = myb1;
    __syncthreads();
    for (int off = 1; off < NTHREADS; off <<= 1) {
        unsigned v = (t >= off) ? ss[t - off] : 0u;
        __syncthreads();
        ss[t] += v;
        __syncthreads();
    }
    unsigned myoff = ss[t] - myb1;
    unsigned btot  = ss[NTHREADS - 1];
    if (t == 0) {
        s_base = btot ? atomicAdd(&g_ncand2, btot) : 0u;
        if (btot && s_base + btot > CAND2_MAX) { atomicExch(&g_ovf, 1u); atomicExch(&g_fb, 1u); }
    }
    __syncthreads();
    if (g_fb) return;
    unsigned base = s_base + myoff;

    // phase 2: write b1-cands + mid histogram
    for (unsigned j = (unsigned)t; j < cnt; j += blockDim.x) {
        uint2 r = g_cand[region + j];
        if ((r.x >> 20) == b1) {
            g_cand2[base++] = r;
            agg_shared_add(s_hmid, (r.x >> 10) & 1023u);
        }
    }
    __syncthreads();
    for (unsigned i = t; i < 1024u; i += blockDim.x) {
        unsigned h = s_hmid[i];
        if (h) atomicAdd(&g_hist_mid[i], h);
    }
}

// ---------------------------------------------------------------------------
// 1 block, 1024 threads: select mid bin b2 from g_hist_mid, then low-bit
// histogram of matching g_cand2 entries, select b3 -> exact threshold key.
__global__ void selmid_kernel() {
    if (g_fb) return;
    __shared__ unsigned s[1024];
    __shared__ unsigned s_b2, s_r2;
    int t = threadIdx.x;
    unsigned r1 = g_r1;

    unsigned local = g_hist_mid[t];
    s[t] = local;
    __syncthreads();
    for (int off = 1; off < 1024; off <<= 1) {
        unsigned v = (t >= off) ? s[t - off] : 0u;
        __syncthreads();
        s[t] += v;
        __syncthreads();
    }
    unsigned incl   = s[t];
    unsigned before = incl - local;
    if (r1 > before && r1 <= incl) { s_b2 = (unsigned)t; s_r2 = r1 - before; }
    __syncthreads();

    unsigned b2 = s_b2;
    unsigned r2 = s_r2;

    // low-10-bit histogram of cand2 entries in (b1, b2)
    s[t] = 0u;
    __syncthreads();
    unsigned nc2 = g_ncand2;
    for (unsigned j = (unsigned)t; j < nc2; j += blockDim.x) {
        unsigned k = g_cand2[j].x;
        if (((k >> 10) & 1023u) == b2) atomicAdd(&s[k & 1023u], 1u);
    }
    __syncthreads();

    // scan low hist
    unsigned local2 = s[t];
    __syncthreads();
    s[t] = local2;
    __syncthreads();
    for (int off = 1; off < 1024; off <<= 1) {
        unsigned v = (t >= off) ? s[t - off] : 0u;
        __syncthreads();
        s[t] += v;
        __syncthreads();
    }
    unsigned incl2   = s[t];
    unsigned before2 = incl2 - local2;
    if (r2 > before2 && r2 <= incl2) {
        g_thr_key = (g_b1 << 20) | (b2 << 10) | (unsigned)t;
    }
}

// ---------------------------------------------------------------------------
// Normal: rewrite kept b1-candidates. Fallback: block 0 exact 3-level select.
__global__ void finalize2_kernel(const float* __restrict__ xs,
                                 const float* __restrict__ ms,
                                 const int* __restrict__ t_ptr,
                                 const float* __restrict__ sparsity,
                                 float* __restrict__ out,
                                 unsigned n) {
    if (g_fb) {
        if (blockIdx.x != 0) return;
        __shared__ unsigned sh[4096];
        __shared__ unsigned sv[4];
        float tf = read_tf(t_ptr);
        unsigned R = rank_R(sparsity, n);
        int t = threadIdx.x;

        for (unsigned i = t; i < 4096u; i += blockDim.x) sh[i] = 0u;
        __syncthreads();
        for (unsigned i = t; i < n; i += blockDim.x)
            atomicAdd(&sh[key_of(xs[i], ms[i], tf) >> 20], 1u);
        __syncthreads();
        if (t == 0) {
            unsigned run = 0u;
            for (unsigned b = 0; b < 4096u; b++) {
                if (R <= run + sh[b]) { sv[0] = b; sv[1] = R - run; break; }
                run += sh[b];
            }
        }
        __syncthreads();
        unsigned b1 = sv[0], r1 = sv[1];

        for (unsigned i = t; i < 1024u; i += blockDim.x) sh[i] = 0u;
        __syncthreads();
        for (unsigned i = t; i < n; i += blockDim.x) {
            unsigned k = key_of(xs[i], ms[i], tf);
            if ((k >> 20) == b1) atomicAdd(&sh[(k >> 10) & 1023u], 1u);
        }
        __syncthreads();
        if (t == 0) {
            unsigned run = 0u;
            for (unsigned b = 0; b < 1024u; b++) {
                if (r1 <= run + sh[b]) { sv[2] = b; sv[1] = r1 - run; break; }
                run += sh[b];
            }
        }
        __syncthreads();
        unsigned b2 = sv[2], r2 = sv[1];
        unsigned pre = (b1 << 10) | b2;

        for (unsigned i = t; i < 1024u; i += blockDim.x) sh[i] = 0u;
        __syncthreads();
        for (unsigned i = t; i < n; i += blockDim.x) {
            unsigned k = key_of(xs[i], ms[i], tf);
            if ((k >> 10) == pre) atomicAdd(&sh[k & 1023u], 1u);
        }
        __syncthreads();
        if (t == 0) {
            unsigned run = 0u;
            for (unsigned b = 0; b < 1024u; b++) {
                if (r2 <= run + sh[b]) { sv[3] = (pre << 10) | b; break; }
                run += sh[b];
            }
        }
        __syncthreads();
        unsigned thr = sv[3];

        for (unsigned i = t; i < n; i += blockDim.x) {
            unsigned k = key_of(xs[i], ms[i], tf);
            out[i] = (k >= thr) ? xs[i] : 0.0f;
        }
        return;
    }

    unsigned thr = g_thr_key;
    unsigned nc2 = g_ncand2;
    unsigned stride = gridDim.x * blockDim.x;
    for (unsigned j = blockIdx.x * blockDim.x + threadIdx.x; j < nc2; j += stride) {
        uint2 r = g_cand2[j];
        if (r.x >= thr) out[r.y] = xs[r.y];
    }
}

// ---------------------------------------------------------------------------
extern "C" void kernel_launch(void* const* d_in, const int* in_sizes, int n_in,
                              void* d_out, int out_size) {
    const float* xs = (const float*)d_in[0];
    const float* ms = (const float*)d_in[1];
    const float* sp = (const float*)d_in[2];
    // d_in[3] = mask (unused by the reference computation)
    const int* t_ptr = (n_in >= 5) ? (const int*)d_in[4] : nullptr;

    unsigned n = (unsigned)in_sizes[0];
    float* out = (float*)d_out;

    zero_kernel<<<1, 1024>>>();
    sample_kernel<<<264, 256>>>(xs, ms, t_ptr, sp, n);
    passA_kernel<<<NBLOCKS, NTHREADS>>>(xs, ms, t_ptr, out, n);
    candfilter_kernel<<<NBLOCKS, NTHREADS>>>(xs, sp, out, n);
    selmid_kernel<<<1, 1024>>>();
    finalize2_kernel<<<64, 256>>>(xs, ms, t_ptr, sp, out, n);
}

// round 6
// speedup vs baseline: 4.7558x; 4.7558x over previous
#include <cuda_runtime.h>
#include <stdint.h>

// ---------------------------------------------------------------------------
// MagnitudePruning via sampled-window radix select on s = t*magnitude + |x|
// (monotone surrogate: division by uniform (t+1) preserves rank).
//
// zero    : clear hist2 (1M bins) + counters
// sample  : ~1M strided samples -> 4096-bin hist -> window [b_lo,b_hi]
// passA   : ONE full fused pass: exact below-count, final out for
//           out-of-window elems, compact in-window candidates to per-block
//           regions, shared window histogram
// resolve : persistent fused tail (all 1184 blocks resident):
//           A: select b1/r1; finalize non-b1 cands; hist2 of b1 cands
//           B: 1024 blocks -> partial sums of hist2
//           C: block 0 -> exact threshold key
//           D: all blocks -> apply thr to own region's b1 cands
//           (exact single-block fallback if window missed / overflow)
// ---------------------------------------------------------------------------

#define SAMP_BINS  4096u          // top 12 bits
#define WBINS      1024u          // window width cap (bins)
#define HIST2_SIZE (1u << 20)     // low 20 bits
#define NBLOCKS    1184u
#define NTHREADS   256u
#define TILE_F4    512u           // float4s per tile (2048 elements)
#define TILE_ELEM  2048u
#define PER_BLOCK  40960u         // candidate region capacity per block

__device__ unsigned g_samp_hist[SAMP_BINS];
__device__ unsigned g_whist[WBINS];
__device__ unsigned g_hist2[HIST2_SIZE];
__device__ unsigned g_partial[1024];
__device__ unsigned g_below;
__device__ unsigned g_done;        // sample grid arrival
__device__ unsigned g_d2;          // resolve phase A arrival
__device__ unsigned g_d3;          // resolve phase B arrival
__device__ unsigned g_thr_ready;
__device__ unsigned g_ovf;
__device__ unsigned g_blo, g_bhi;
__device__ unsigned g_thr_key;
__device__ unsigned g_blk_cnt[NBLOCKS];
__device__ uint2    g_cand[NBLOCKS * PER_BLOCK];

__device__ __forceinline__ unsigned key_of(float x, float m, float tf) {
    float s = __fadd_rn(__fmul_rn(tf, m), fabsf(x));
    return __float_as_uint(s);
}
__device__ __forceinline__ float read_tf(const int* t_ptr) {
    return t_ptr ? (float)(*t_ptr) : 1.0f;
}
__device__ __forceinline__ unsigned rank_R(const float* sp, unsigned n) {
    float fidx = floorf(__fsub_rn(__fmul_rn(sp[0], (float)n), 1.0f));
    long long idx = (long long)fidx;
    if (idx < 0) idx = 0;
    if (idx > (long long)(n - 1)) idx = (long long)(n - 1);
    return (unsigned)idx + 1u;
}
__device__ __forceinline__ void agg_shared_add(unsigned* hist, unsigned bin) {
    unsigned act    = __activemask();
    unsigned peers  = __match_any_sync(act, bin);
    int      leader = __ffs(peers) - 1;
    if ((int)(threadIdx.x & 31) == leader)
        atomicAdd(&hist[bin], (unsigned)__popc(peers));
}

// ---------------------------------------------------------------------------
__global__ void zero_kernel() {
    unsigned stride = gridDim.x * blockDim.x;
    unsigned tid = blockIdx.x * blockDim.x + threadIdx.x;
    for (unsigned i = tid; i < HIST2_SIZE; i += stride) g_hist2[i] = 0u;
    for (unsigned i = tid; i < SAMP_BINS;  i += stride) g_samp_hist[i] = 0u;
    for (unsigned i = tid; i < WBINS;      i += stride) g_whist[i] = 0u;
    for (unsigned i = tid; i < 1024u;      i += stride) g_partial[i] = 0u;
    if (tid == 0) {
        g_below = 0u; g_done = 0u; g_d2 = 0u; g_d3 = 0u;
        g_thr_ready = 0u; g_ovf = 0u;
    }
}

// ---------------------------------------------------------------------------
// Sample ~1M elements, 4096-bin hist; the last block computes the window.
__global__ void sample_kernel(const float* __restrict__ xs,
                              const float* __restrict__ ms,
                              const int* __restrict__ t_ptr,
                              const float* __restrict__ sparsity,
                              unsigned n) {
    __shared__ unsigned sh[SAMP_BINS];
    for (unsigned i = threadIdx.x; i < SAMP_BINS; i += blockDim.x) sh[i] = 0u;
    __syncthreads();

    float tf = read_tf(t_ptr);
    unsigned n4 = n >> 2;
    unsigned stride4 = n4 / 262144u; if (stride4 == 0u) stride4 = 1u;
    unsigned nsamp4  = n4 / stride4;
    const float4* x4 = (const float4*)xs;
    const float4* m4 = (const float4*)ms;

    unsigned gstride = gridDim.x * blockDim.x;
    for (unsigned i = blockIdx.x * blockDim.x + threadIdx.x; i < nsamp4; i += gstride) {
        unsigned idx = i * stride4;
        float4 xv = x4[idx];
        float4 mv = m4[idx];
        agg_shared_add(sh, key_of(xv.x, mv.x, tf) >> 20);
        agg_shared_add(sh, key_of(xv.y, mv.y, tf) >> 20);
        agg_shared_add(sh, key_of(xv.z, mv.z, tf) >> 20);
        agg_shared_add(sh, key_of(xv.w, mv.w, tf) >> 20);
    }
    __syncthreads();
    for (unsigned i = threadIdx.x; i < SAMP_BINS; i += blockDim.x) {
        unsigned c = sh[i];
        if (c) atomicAdd(&g_samp_hist[i], c);
    }
    __threadfence();

    __shared__ unsigned slast;
    if (threadIdx.x == 0)
        slast = (atomicAdd(&g_done, 1u) == gridDim.x - 1u) ? 1u : 0u;
    __syncthreads();
    if (!slast) return;

    // ---- last block: compute window ----
    __shared__ unsigned sscan[256];
    __shared__ unsigned svlo, svhi;
    int t = threadIdx.x;               // 256 threads, 16 bins each
    unsigned loc[16];
    unsigned lsum = 0u;
    #pragma unroll
    for (int j = 0; j < 16; j++) { loc[j] = g_samp_hist[t * 16 + j]; lsum += loc[j]; }
    sscan[t] = lsum;
    __syncthreads();
    for (int off = 1; off < 256; off <<= 1) {
        unsigned v = (t >= off) ? sscan[t - off] : 0u;
        __syncthreads();
        sscan[t] += v;
        __syncthreads();
    }
    unsigned incl  = sscan[t];
    unsigned total = sscan[255];
    unsigned before = incl - lsum;

    unsigned R = rank_R(sparsity, n);
    float f = (float)R / (float)n;
    float tlo = (f - 0.01f) * (float)total;
    float thi = (f + 0.01f) * (float)total + 1.0f;
    unsigned slo = (tlo < 1.0f) ? 1u : (unsigned)tlo;
    if (slo > total) slo = total;
    unsigned shi = (thi < 1.0f) ? 1u : (unsigned)thi;
    if (shi > total) shi = total;
    if (shi < slo) shi = slo;

    if (slo > before && slo <= incl) {
        unsigned run = before;
        #pragma unroll
        for (int j = 0; j < 16; j++) {
            if (slo <= run + loc[j]) { svlo = (unsigned)(t * 16 + j); break; }
            run += loc[j];
        }
    }
    if (shi > before && shi <= incl) {
        unsigned run = before;
        #pragma unroll
        for (int j = 0; j < 16; j++) {
            if (shi <= run + loc[j]) { svhi = (unsigned)(t * 16 + j); break; }
            run += loc[j];
        }
    }
    __syncthreads();
    if (t == 0) {
        unsigned blo = svlo, bhi = svhi;
        if (bhi < blo) bhi = blo;
        if (bhi - blo + 1u > WBINS) bhi = blo + WBINS - 1u;
        g_blo = blo; g_bhi = bhi;
    }
}

// ---------------------------------------------------------------------------
// The single fused full pass.
__global__ void passA_kernel(const float* __restrict__ xs,
                             const float* __restrict__ ms,
                             const int* __restrict__ t_ptr,
                             float* __restrict__ out,
                             unsigned n) {
    __shared__ uint2    s_buf[TILE_ELEM];
    __shared__ unsigned s_whist[WBINS];
    __shared__ unsigned s_cnt;
    __shared__ unsigned s_red[NTHREADS];

    for (unsigned i = threadIdx.x; i < WBINS; i += blockDim.x) s_whist[i] = 0u;

    float tf = read_tf(t_ptr);
    unsigned b_lo = g_blo, b_hi = g_bhi;
    unsigned n4 = n >> 2;
    const float4* x4 = (const float4*)xs;
    const float4* m4 = (const float4*)ms;
    float4* o4 = (float4*)out;

    unsigned region = blockIdx.x * PER_BLOCK;
    unsigned nreg = 0u;
    unsigned below = 0u;
    unsigned ntiles = (n4 + TILE_F4 - 1u) / TILE_F4;

    for (unsigned tile = blockIdx.x; tile < ntiles; tile += gridDim.x) {
        if (threadIdx.x == 0) s_cnt = 0u;
        __syncthreads();

        unsigned tbase = tile * TILE_F4;
        #pragma unroll
        for (int k = 0; k < 2; k++) {
            unsigned i = tbase + (unsigned)k * NTHREADS + threadIdx.x;
            if (i < n4) {
                float4 xv = x4[i];
                float4 mv = m4[i];
                unsigned e = i * 4u;
                unsigned kk[4];
                kk[0] = key_of(xv.x, mv.x, tf);
                kk[1] = key_of(xv.y, mv.y, tf);
                kk[2] = key_of(xv.z, mv.z, tf);
                kk[3] = key_of(xv.w, mv.w, tf);
                float vv[4] = {xv.x, xv.y, xv.z, xv.w};
                float ov[4];
                #pragma unroll
                for (int j = 0; j < 4; j++) {
                    unsigned top = kk[j] >> 20;
                    below += (top < b_lo) ? 1u : 0u;
                    ov[j] = (top > b_hi) ? vv[j] : 0.0f;
                    if (top >= b_lo && top <= b_hi) {
                        unsigned pos = atomicAdd(&s_cnt, 1u);
                        s_buf[pos] = make_uint2(kk[j], e + (unsigned)j);
                        agg_shared_add(s_whist, top - b_lo);
                    }
                }
                o4[i] = make_float4(ov[0], ov[1], ov[2], ov[3]);
            }
        }
        __syncthreads();

        unsigned cnt = s_cnt;
        if (cnt) {
            if (nreg + cnt <= PER_BLOCK) {
                for (unsigned j = threadIdx.x; j < cnt; j += blockDim.x)
                    g_cand[region + nreg + j] = s_buf[j];
                nreg += cnt;
            } else {
                if (threadIdx.x == 0) atomicExch(&g_ovf, 1u);
            }
        }
        __syncthreads();
    }

    // scalar tail (n % 4)
    if (blockIdx.x == 0 && threadIdx.x == 0) {
        for (unsigned i = n4 << 2; i < n; i++) {
            unsigned k = key_of(xs[i], ms[i], tf);
            unsigned top = k >> 20;
            below += (top < b_lo) ? 1u : 0u;
            out[i] = (top > b_hi) ? xs[i] : 0.0f;
            if (top >= b_lo && top <= b_hi) {
                if (nreg < PER_BLOCK) {
                    g_cand[region + nreg] = make_uint2(k, i);
                    nreg++;
                    atomicAdd(&s_whist[top - b_lo], 1u);
                } else {
                    atomicExch(&g_ovf, 1u);
                }
            }
        }
    }
    __syncthreads();

    if (threadIdx.x == 0) g_blk_cnt[blockIdx.x] = nreg;

    s_red[threadIdx.x] = below;
    __syncthreads();
    for (int off = NTHREADS / 2; off > 0; off >>= 1) {
        if ((int)threadIdx.x < off) s_red[threadIdx.x] += s_red[threadIdx.x + off];
        __syncthreads();
    }
    if (threadIdx.x == 0 && s_red[0]) atomicAdd(&g_below, s_red[0]);

    for (unsigned i = threadIdx.x; i < WBINS; i += blockDim.x) {
        unsigned c = s_whist[i];
        if (c) atomicAdd(&g_whist[i], c);
    }
}

// ---------------------------------------------------------------------------
// Persistent fused tail. All NBLOCKS blocks are simultaneously resident
// (256 threads, <=8 blocks/SM), so grid-wide spin phases are deadlock-free.
__global__ void __launch_bounds__(NTHREADS, 8)
resolve_kernel(const float* __restrict__ xs,
               const float* __restrict__ ms,
               const int* __restrict__ t_ptr,
               const float* __restrict__ sparsity,
               float* __restrict__ out,
               unsigned n) {
    __shared__ unsigned ss[NTHREADS];
    __shared__ unsigned sb1, sr1;
    __shared__ unsigned sfh[4096];     // fallback scratch (also big enough reuse)
    __shared__ unsigned sv[4];
    int t = threadIdx.x;

    // ---- select b1/r1 from g_whist + g_below (redundant in every block) ----
    if (t == 0) { sb1 = 0xFFFFFFFFu; sr1 = 1u; }
    unsigned c[4];
    unsigned local = 0u;
    #pragma unroll
    for (int j = 0; j < 4; j++) { c[j] = g_whist[t * 4 + j]; local += c[j]; }
    ss[t] = local;
    __syncthreads();
    for (int off = 1; off < NTHREADS; off <<= 1) {
        unsigned v = (t >= off) ? ss[t - off] : 0u;
        __syncthreads();
        ss[t] += v;
        __syncthreads();
    }
    unsigned incl   = ss[t];
    unsigned total  = ss[NTHREADS - 1];
    unsigned before = incl - local;

    unsigned below = g_below;
    unsigned R = rank_R(sparsity, n);
    bool fb = (below >= R) || ((R - below) > total) || (g_ovf != 0u);
    unsigned Rp = R - below;

    if (!fb && Rp > before && Rp <= incl) {
        unsigned run = before;
        #pragma unroll
        for (int j = 0; j < 4; j++) {
            if (Rp <= run + c[j]) {
                sb1 = g_blo + (unsigned)(t * 4 + j);
                sr1 = Rp - run;
                break;
            }
            run += c[j];
        }
    }
    __syncthreads();

    // ---- fallback: block 0 exact 3-level radix over full data ----
    if (fb) {
        if (blockIdx.x != 0) return;
        float tf = read_tf(t_ptr);

        for (unsigned i = t; i < 4096u; i += blockDim.x) sfh[i] = 0u;
        __syncthreads();
        for (unsigned i = t; i < n; i += blockDim.x)
            atomicAdd(&sfh[key_of(xs[i], ms[i], tf) >> 20], 1u);
        __syncthreads();
        if (t == 0) {
            unsigned run = 0u;
            for (unsigned b = 0; b < 4096u; b++) {
                if (R <= run + sfh[b]) { sv[0] = b; sv[1] = R - run; break; }
                run += sfh[b];
            }
        }
        __syncthreads();
        unsigned b1 = sv[0], r1 = sv[1];

        for (unsigned i = t; i < 1024u; i += blockDim.x) sfh[i] = 0u;
        __syncthreads();
        for (unsigned i = t; i < n; i += blockDim.x) {
            unsigned k = key_of(xs[i], ms[i], tf);
            if ((k >> 20) == b1) atomicAdd(&sfh[(k >> 10) & 1023u], 1u);
        }
        __syncthreads();
        if (t == 0) {
            unsigned run = 0u;
            for (unsigned b = 0; b < 1024u; b++) {
                if (r1 <= run + sfh[b]) { sv[2] = b; sv[1] = r1 - run; break; }
                run += sfh[b];
            }
        }
        __syncthreads();
        unsigned b2 = sv[2], r2 = sv[1];
        unsigned pre = (b1 << 10) | b2;

        for (unsigned i = t; i < 1024u; i += blockDim.x) sfh[i] = 0u;
        __syncthreads();
        for (unsigned i = t; i < n; i += blockDim.x) {
            unsigned k = key_of(xs[i], ms[i], tf);
            if ((k >> 10) == pre) atomicAdd(&sfh[k & 1023u], 1u);
        }
        __syncthreads();
        if (t == 0) {
            unsigned run = 0u;
            for (unsigned b = 0; b < 1024u; b++) {
                if (r2 <= run + sfh[b]) { sv[3] = (pre << 10) | b; break; }
                run += sfh[b];
            }
        }
        __syncthreads();
        unsigned thr = sv[3];
        for (unsigned i = t; i < n; i += blockDim.x) {
            unsigned k = key_of(xs[i], ms[i], tf);
            out[i] = (k >= thr) ? xs[i] : 0.0f;
        }
        return;
    }

    unsigned b1 = sb1;
    unsigned r1 = sr1;
    unsigned cnt    = g_blk_cnt[blockIdx.x];
    unsigned region = blockIdx.x * PER_BLOCK;

    // ---- phase A: finalize non-b1 cands; hist2 of b1 cands ----
    for (unsigned j = (unsigned)t; j < cnt; j += blockDim.x) {
        uint2 r = g_cand[region + j];
        unsigned top = r.x >> 20;
        if (top > b1) out[r.y] = xs[r.y];
        else if (top == b1) atomicAdd(&g_hist2[r.x & 0xFFFFFu], 1u);
    }
    __threadfence();
    __syncthreads();
    if (t == 0) atomicAdd(&g_d2, 1u);

    // ---- phase B: first 1024 blocks sum their 1K-bin chunk ----
    if (blockIdx.x < 1024u) {
        if (t == 0) { while (atomicAdd(&g_d2, 0u) < gridDim.x) {} }
        __syncthreads();
        unsigned base = blockIdx.x * 1024u;
        unsigned sum = 0u;
        for (unsigned i = (unsigned)t; i < 1024u; i += blockDim.x)
            sum += g_hist2[base + i];
        ss[t] = sum;
        __syncthreads();
        for (int off = NTHREADS / 2; off > 0; off >>= 1) {
            if (t < off) ss[t] += ss[t + off];
            __syncthreads();
        }
        if (t == 0) {
            g_partial[blockIdx.x] = ss[0];
            __threadfence();
            atomicAdd(&g_d3, 1u);
        }
        __syncthreads();
    }

    // ---- phase C: block 0 computes the exact threshold key ----
    if (blockIdx.x == 0) {
        if (t == 0) { while (atomicAdd(&g_d3, 0u) < 1024u) {} }
        __syncthreads();

        unsigned p[4];
        unsigned loc = 0u;
        #pragma unroll
        for (int j = 0; j < 4; j++) { p[j] = g_partial[t * 4 + j]; loc += p[j]; }
        ss[t] = loc;
        __syncthreads();
        for (int off = 1; off < NTHREADS; off <<= 1) {
            unsigned v = (t >= off) ? ss[t - off] : 0u;
            __syncthreads();
            ss[t] += v;
            __syncthreads();
        }
        unsigned inc2 = ss[t];
        unsigned bef2 = inc2 - loc;
        if (t == 0) { sv[0] = 0u; sv[1] = 1u; }
        __syncthreads();
        if (r1 > bef2 && r1 <= inc2) {
            unsigned run = bef2;
            #pragma unroll
            for (int j = 0; j < 4; j++) {
                if (r1 <= run + p[j]) { sv[0] = (unsigned)(t * 4 + j); sv[1] = r1 - run; break; }
                run += p[j];
            }
        }
        __syncthreads();
        unsigned chunk = sv[0];
        unsigned r2    = sv[1];

        unsigned q[4];
        unsigned loc3 = 0u;
        #pragma unroll
        for (int j = 0; j < 4; j++) { q[j] = g_hist2[chunk * 1024u + t * 4 + j]; loc3 += q[j]; }
        ss[t] = loc3;
        __syncthreads();
        for (int off = 1; off < NTHREADS; off <<= 1) {
            unsigned v = (t >= off) ? ss[t - off] : 0u;
            __syncthreads();
            ss[t] += v;
            __syncthreads();
        }
        unsigned inc3 = ss[t];
        unsigned bef3 = inc3 - loc3;
        if (r2 > bef3 && r2 <= inc3) {
            unsigned run = bef3;
            #pragma unroll
            for (int j = 0; j < 4; j++) {
                if (r2 <= run + q[j]) {
                    g_thr_key = (b1 << 20) | (chunk * 1024u + (unsigned)(t * 4 + j));
                    break;
                }
                run += q[j];
            }
        }
        __syncthreads();
        if (t == 0) { __threadfence(); atomicExch(&g_thr_ready, 1u); }
    }

    // ---- phase D: all blocks apply thr to own region's b1 cands ----
    if (t == 0) { while (atomicAdd(&g_thr_ready, 0u) == 0u) {} }
    __syncthreads();
    unsigned thr = g_thr_key;
    for (unsigned j = (unsigned)t; j < cnt; j += blockDim.x) {
        uint2 r = g_cand[region + j];
        if ((r.x >> 20) == b1 && r.x >= thr) out[r.y] = xs[r.y];
    }
}

// ---------------------------------------------------------------------------
extern "C" void kernel_launch(void* const* d_in, const int* in_sizes, int n_in,
                              void* d_out, int out_size) {
    const float* xs = (const float*)d_in[0];
    const float* ms = (const float*)d_in[1];
    const float* sp = (const float*)d_in[2];
    // d_in[3] = mask (unused by the reference computation)
    const int* t_ptr = (n_in >= 5) ? (const int*)d_in[4] : nullptr;

    unsigned n = (unsigned)in_sizes[0];
    float* out = (float*)d_out;

    zero_kernel<<<296, 256>>>();
    sample_kernel<<<264, 256>>>(xs, ms, t_ptr, sp, n);
    passA_kernel<<<NBLOCKS, NTHREADS>>>(xs, ms, t_ptr, out, n);
    resolve_kernel<<<NBLOCKS, NTHREADS>>>(xs, ms, t_ptr, sp, out, n);
}

// round 7
// speedup vs baseline: 6.0034x; 1.2623x over previous
#include <cuda_runtime.h>
#include <stdint.h>

// ---------------------------------------------------------------------------
// MagnitudePruning via sampled-window radix select on s = t*magnitude + |x|
// (monotone surrogate: division by uniform (t+1) preserves rank).
//
// zero    : clear small histograms/counters (tiny)
// sample  : ~1M strided samples -> 4096-bin hist -> window [b_lo,b_hi] (+-0.3%)
// passA   : ONE full fused pass: exact below-count, final out for
//           out-of-window elems, compact in-window cands to per-block regions
// resolve : persistent fused tail (all 1184 blocks resident):
//           A : finalize top>b1 cands; 2048-bin mid hist (bits [9,20)) of b1
//           C1: block 0 -> select b2, r2
//           B : finalize mid>b2 cands; stash mid==b2 cands; 512-bin low hist
//           C2: block 0 -> exact threshold key
//           D : apply thr from shared stash
//           (exact single-block fallback if window missed / overflow)
// ---------------------------------------------------------------------------

#define SAMP_BINS  4096u
#define WBINS      1024u
#define NBLOCKS    1184u
#define NTHREADS   256u
#define TILE_F4    512u
#define PER_BLOCK  40960u
#define STASH_MAX  1024u

__device__ unsigned g_samp_hist[SAMP_BINS];
__device__ unsigned g_whist[WBINS];
__device__ unsigned g_hist_mid[2048];
__device__ unsigned g_hist_low[512];
__device__ unsigned g_below;
__device__ unsigned g_done;        // sample arrival
__device__ unsigned g_d2;          // resolve phase A arrival
__device__ unsigned g_d3;          // resolve phase B arrival
__device__ unsigned g_rdy1;        // b2 published
__device__ unsigned g_rdy2;        // thr published
__device__ unsigned g_ovf;
__device__ unsigned g_blo, g_bhi;
__device__ unsigned g_b2v, g_r2v;
__device__ unsigned g_thr_key;
__device__ unsigned g_blk_cnt[NBLOCKS];
__device__ uint2    g_cand[NBLOCKS * PER_BLOCK];

__device__ __forceinline__ unsigned key_of(float x, float m, float tf) {
    float s = __fadd_rn(__fmul_rn(tf, m), fabsf(x));
    return __float_as_uint(s);
}
__device__ __forceinline__ float read_tf(const int* t_ptr) {
    return t_ptr ? (float)(*t_ptr) : 1.0f;
}
__device__ __forceinline__ unsigned rank_R(const float* sp, unsigned n) {
    float fidx = floorf(__fsub_rn(__fmul_rn(sp[0], (float)n), 1.0f));
    long long idx = (long long)fidx;
    if (idx < 0) idx = 0;
    if (idx > (long long)(n - 1)) idx = (long long)(n - 1);
    return (unsigned)idx + 1u;
}
__device__ __forceinline__ void agg_shared_add(unsigned* hist, unsigned bin) {
    unsigned act    = __activemask();
    unsigned peers  = __match_any_sync(act, bin);
    int      leader = __ffs(peers) - 1;
    if ((int)(threadIdx.x & 31) == leader)
        atomicAdd(&hist[bin], (unsigned)__popc(peers));
}

// ---------------------------------------------------------------------------
__global__ void zero_kernel() {
    unsigned tid = blockIdx.x * blockDim.x + threadIdx.x;
    unsigned stride = gridDim.x * blockDim.x;
    for (unsigned i = tid; i < SAMP_BINS; i += stride) g_samp_hist[i] = 0u;
    for (unsigned i = tid; i < WBINS;     i += stride) g_whist[i] = 0u;
    for (unsigned i = tid; i < 2048u;     i += stride) g_hist_mid[i] = 0u;
    for (unsigned i = tid; i < 512u;      i += stride) g_hist_low[i] = 0u;
    if (tid == 0) {
        g_below = 0u; g_done = 0u; g_d2 = 0u; g_d3 = 0u;
        g_rdy1 = 0u; g_rdy2 = 0u; g_ovf = 0u;
    }
}

// ---------------------------------------------------------------------------
__global__ void sample_kernel(const float* __restrict__ xs,
                              const float* __restrict__ ms,
                              const int* __restrict__ t_ptr,
                              const float* __restrict__ sparsity,
                              unsigned n) {
    __shared__ unsigned sh[SAMP_BINS];
    for (unsigned i = threadIdx.x; i < SAMP_BINS; i += blockDim.x) sh[i] = 0u;
    __syncthreads();

    float tf = read_tf(t_ptr);
    unsigned n4 = n >> 2;
    unsigned stride4 = n4 / 262144u; if (stride4 == 0u) stride4 = 1u;
    unsigned nsamp4  = n4 / stride4;
    const float4* x4 = (const float4*)xs;
    const float4* m4 = (const float4*)ms;

    unsigned gstride = gridDim.x * blockDim.x;
    for (unsigned i = blockIdx.x * blockDim.x + threadIdx.x; i < nsamp4; i += gstride) {
        unsigned idx = i * stride4;
        float4 xv = x4[idx];
        float4 mv = m4[idx];
        agg_shared_add(sh, key_of(xv.x, mv.x, tf) >> 20);
        agg_shared_add(sh, key_of(xv.y, mv.y, tf) >> 20);
        agg_shared_add(sh, key_of(xv.z, mv.z, tf) >> 20);
        agg_shared_add(sh, key_of(xv.w, mv.w, tf) >> 20);
    }
    __syncthreads();
    for (unsigned i = threadIdx.x; i < SAMP_BINS; i += blockDim.x) {
        unsigned c = sh[i];
        if (c) atomicAdd(&g_samp_hist[i], c);
    }
    __threadfence();

    __shared__ unsigned slast;
    if (threadIdx.x == 0)
        slast = (atomicAdd(&g_done, 1u) == gridDim.x - 1u) ? 1u : 0u;
    __syncthreads();
    if (!slast) return;

    // ---- last block: compute window, margin +-0.3% of rank ----
    __shared__ unsigned sscan[256];
    __shared__ unsigned svlo, svhi;
    int t = threadIdx.x;
    unsigned loc[16];
    unsigned lsum = 0u;
    #pragma unroll
    for (int j = 0; j < 16; j++) { loc[j] = g_samp_hist[t * 16 + j]; lsum += loc[j]; }
    sscan[t] = lsum;
    __syncthreads();
    for (int off = 1; off < 256; off <<= 1) {
        unsigned v = (t >= off) ? sscan[t - off] : 0u;
        __syncthreads();
        sscan[t] += v;
        __syncthreads();
    }
    unsigned incl  = sscan[t];
    unsigned total = sscan[255];
    unsigned before = incl - lsum;

    unsigned R = rank_R(sparsity, n);
    float f = (float)R / (float)n;
    float tlo = (f - 0.003f) * (float)total;
    float thi = (f + 0.003f) * (float)total + 1.0f;
    unsigned slo = (tlo < 1.0f) ? 1u : (unsigned)tlo;
    if (slo > total) slo = total;
    unsigned shi = (thi < 1.0f) ? 1u : (unsigned)thi;
    if (shi > total) shi = total;
    if (shi < slo) shi = slo;

    if (slo > before && slo <= incl) {
        unsigned run = before;
        #pragma unroll
        for (int j = 0; j < 16; j++) {
            if (slo <= run + loc[j]) { svlo = (unsigned)(t * 16 + j); break; }
            run += loc[j];
        }
    }
    if (shi > before && shi <= incl) {
        unsigned run = before;
        #pragma unroll
        for (int j = 0; j < 16; j++) {
            if (shi <= run + loc[j]) { svhi = (unsigned)(t * 16 + j); break; }
            run += loc[j];
        }
    }
    __syncthreads();
    if (t == 0) {
        unsigned blo = svlo, bhi = svhi;
        if (bhi < blo) bhi = blo;
        if (bhi - blo + 1u > WBINS) bhi = blo + WBINS - 1u;
        g_blo = blo; g_bhi = bhi;
    }
}

// ---------------------------------------------------------------------------
__global__ void passA_kernel(const float* __restrict__ xs,
                             const float* __restrict__ ms,
                             const int* __restrict__ t_ptr,
                             float* __restrict__ out,
                             unsigned n) {
    __shared__ uint2    s_buf[2048];
    __shared__ unsigned s_whist[WBINS];
    __shared__ unsigned s_cnt;
    __shared__ unsigned s_red[NTHREADS];

    for (unsigned i = threadIdx.x; i < WBINS; i += blockDim.x) s_whist[i] = 0u;

    float tf = read_tf(t_ptr);
    unsigned b_lo = g_blo, b_hi = g_bhi;
    unsigned n4 = n >> 2;
    const float4* x4 = (const float4*)xs;
    const float4* m4 = (const float4*)ms;
    float4* o4 = (float4*)out;

    unsigned region = blockIdx.x * PER_BLOCK;
    unsigned nreg = 0u;
    unsigned below = 0u;
    unsigned ntiles = (n4 + TILE_F4 - 1u) / TILE_F4;

    for (unsigned tile = blockIdx.x; tile < ntiles; tile += gridDim.x) {
        if (threadIdx.x == 0) s_cnt = 0u;
        __syncthreads();

        unsigned tbase = tile * TILE_F4;
        #pragma unroll
        for (int k = 0; k < 2; k++) {
            unsigned i = tbase + (unsigned)k * NTHREADS + threadIdx.x;
            if (i < n4) {
                float4 xv = x4[i];
                float4 mv = m4[i];
                unsigned e = i * 4u;
                unsigned kk[4];
                kk[0] = key_of(xv.x, mv.x, tf);
                kk[1] = key_of(xv.y, mv.y, tf);
                kk[2] = key_of(xv.z, mv.z, tf);
                kk[3] = key_of(xv.w, mv.w, tf);
                float vv[4] = {xv.x, xv.y, xv.z, xv.w};
                float ov[4];
                #pragma unroll
                for (int j = 0; j < 4; j++) {
                    unsigned top = kk[j] >> 20;
                    below += (top < b_lo) ? 1u : 0u;
                    ov[j] = (top > b_hi) ? vv[j] : 0.0f;
                    if (top >= b_lo && top <= b_hi) {
                        unsigned pos = atomicAdd(&s_cnt, 1u);
                        s_buf[pos] = make_uint2(kk[j], e + (unsigned)j);
                        agg_shared_add(s_whist, top - b_lo);
                    }
                }
                o4[i] = make_float4(ov[0], ov[1], ov[2], ov[3]);
            }
        }
        __syncthreads();

        unsigned cnt = s_cnt;
        if (cnt) {
            if (nreg + cnt <= PER_BLOCK) {
                for (unsigned j = threadIdx.x; j < cnt; j += blockDim.x)
                    g_cand[region + nreg + j] = s_buf[j];
                nreg += cnt;
            } else {
                if (threadIdx.x == 0) atomicExch(&g_ovf, 1u);
            }
        }
        __syncthreads();
    }

    if (blockIdx.x == 0 && threadIdx.x == 0) {
        for (unsigned i = n4 << 2; i < n; i++) {
            unsigned k = key_of(xs[i], ms[i], tf);
            unsigned top = k >> 20;
            below += (top < b_lo) ? 1u : 0u;
            out[i] = (top > b_hi) ? xs[i] : 0.0f;
            if (top >= b_lo && top <= b_hi) {
                if (nreg < PER_BLOCK) {
                    g_cand[region + nreg] = make_uint2(k, i);
                    nreg++;
                    atomicAdd(&s_whist[top - b_lo], 1u);
                } else {
                    atomicExch(&g_ovf, 1u);
                }
            }
        }
    }
    __syncthreads();

    if (threadIdx.x == 0) g_blk_cnt[blockIdx.x] = nreg;

    s_red[threadIdx.x] = below;
    __syncthreads();
    for (int off = NTHREADS / 2; off > 0; off >>= 1) {
        if ((int)threadIdx.x < off) s_red[threadIdx.x] += s_red[threadIdx.x + off];
        __syncthreads();
    }
    if (threadIdx.x == 0 && s_red[0]) atomicAdd(&g_below, s_red[0]);

    for (unsigned i = threadIdx.x; i < WBINS; i += blockDim.x) {
        unsigned c = s_whist[i];
        if (c) atomicAdd(&g_whist[i], c);
    }
}

// ---------------------------------------------------------------------------
// Persistent fused tail; all NBLOCKS blocks resident (148 SMs x 8).
__global__ void __launch_bounds__(NTHREADS, 8)
resolve_kernel(const float* __restrict__ xs,
               const float* __restrict__ ms,
               const int* __restrict__ t_ptr,
               const float* __restrict__ sparsity,
               float* __restrict__ out,
               unsigned n) {
    __shared__ unsigned ss[NTHREADS];
    __shared__ unsigned sh[4096];      // reused: mid-hist(2048)/low-hist(512)/fallback
    __shared__ uint2    stash[STASH_MAX];
    __shared__ unsigned sb1, sr1, s_stash;
    __shared__ unsigned sv[4];
    int t = threadIdx.x;

    // ---- select b1/r1 from g_whist + g_below (redundant per block) ----
    if (t == 0) { sb1 = 0xFFFFFFFFu; sr1 = 1u; s_stash = 0u; }
    unsigned c[4];
    unsigned local = 0u;
    #pragma unroll
    for (int j = 0; j < 4; j++) { c[j] = g_whist[t * 4 + j]; local += c[j]; }
    ss[t] = local;
    __syncthreads();
    for (int off = 1; off < NTHREADS; off <<= 1) {
        unsigned v = (t >= off) ? ss[t - off] : 0u;
        __syncthreads();
        ss[t] += v;
        __syncthreads();
    }
    unsigned incl   = ss[t];
    unsigned total  = ss[NTHREADS - 1];
    unsigned before = incl - local;

    unsigned below = g_below;
    unsigned R = rank_R(sparsity, n);
    bool fb = (below >= R) || ((R - below) > total) || (g_ovf != 0u);
    unsigned Rp = R - below;

    if (!fb && Rp > before && Rp <= incl) {
        unsigned run = before;
        #pragma unroll
        for (int j = 0; j < 4; j++) {
            if (Rp <= run + c[j]) {
                sb1 = g_blo + (unsigned)(t * 4 + j);
                sr1 = Rp - run;
                break;
            }
            run += c[j];
        }
    }
    __syncthreads();

    // ---- fallback: block 0 exact 3-level radix over full data ----
    if (fb) {
        if (blockIdx.x != 0) return;
        float tf = read_tf(t_ptr);

        for (unsigned i = t; i < 4096u; i += blockDim.x) sh[i] = 0u;
        __syncthreads();
        for (unsigned i = t; i < n; i += blockDim.x)
            atomicAdd(&sh[key_of(xs[i], ms[i], tf) >> 20], 1u);
        __syncthreads();
        if (t == 0) {
            unsigned run = 0u;
            for (unsigned b = 0; b < 4096u; b++) {
                if (R <= run + sh[b]) { sv[0] = b; sv[1] = R - run; break; }
                run += sh[b];
            }
        }
        __syncthreads();
        unsigned b1 = sv[0], r1 = sv[1];

        for (unsigned i = t; i < 1024u; i += blockDim.x) sh[i] = 0u;
        __syncthreads();
        for (unsigned i = t; i < n; i += blockDim.x) {
            unsigned k = key_of(xs[i], ms[i], tf);
            if ((k >> 20) == b1) atomicAdd(&sh[(k >> 10) & 1023u], 1u);
        }
        __syncthreads();
        if (t == 0) {
            unsigned run = 0u;
            for (unsigned b = 0; b < 1024u; b++) {
                if (r1 <= run + sh[b]) { sv[2] = b; sv[1] = r1 - run; break; }
                run += sh[b];
            }
        }
        __syncthreads();
        unsigned b2 = sv[2], r2 = sv[1];
        unsigned pre = (b1 << 10) | b2;

        for (unsigned i = t; i < 1024u; i += blockDim.x) sh[i] = 0u;
        __syncthreads();
        for (unsigned i = t; i < n; i += blockDim.x) {
            unsigned k = key_of(xs[i], ms[i], tf);
            if ((k >> 10) == pre) atomicAdd(&sh[k & 1023u], 1u);
        }
        __syncthreads();
        if (t == 0) {
            unsigned run = 0u;
            for (unsigned b = 0; b < 1024u; b++) {
                if (r2 <= run + sh[b]) { sv[3] = (pre << 10) | b; break; }
                run += sh[b];
            }
        }
        __syncthreads();
        unsigned thr = sv[3];
        for (unsigned i = t; i < n; i += blockDim.x) {
            unsigned k = key_of(xs[i], ms[i], tf);
            out[i] = (k >= thr) ? xs[i] : 0.0f;
        }
        return;
    }

    unsigned b1 = sb1;
    unsigned r1 = sr1;
    unsigned cnt    = g_blk_cnt[blockIdx.x];
    unsigned region = blockIdx.x * PER_BLOCK;

    // ---- phase A: finalize top>b1; shared 2048-bin mid hist of b1 cands ----
    for (unsigned i = t; i < 2048u; i += blockDim.x) sh[i] = 0u;
    __syncthreads();
    for (unsigned j = (unsigned)t; j < cnt; j += blockDim.x) {
        uint2 r = g_cand[region + j];
        unsigned top = r.x >> 20;
        if (top > b1) out[r.y] = xs[r.y];
        else if (top == b1) agg_shared_add(sh, (r.x >> 9) & 2047u);
    }
    __syncthreads();
    for (unsigned i = t; i < 2048u; i += blockDim.x) {
        unsigned h = sh[i];
        if (h) atomicAdd(&g_hist_mid[i], h);
    }
    __threadfence();
    __syncthreads();
    if (t == 0) atomicAdd(&g_d2, 1u);

    // ---- phase C1: block 0 selects b2, r2 ----
    if (blockIdx.x == 0) {
        if (t == 0) { while (atomicAdd(&g_d2, 0u) < gridDim.x) {} }
        __syncthreads();
        unsigned p[8];
        unsigned loc = 0u;
        #pragma unroll
        for (int j = 0; j < 8; j++) { p[j] = g_hist_mid[t * 8 + j]; loc += p[j]; }
        ss[t] = loc;
        __syncthreads();
        for (int off = 1; off < NTHREADS; off <<= 1) {
            unsigned v = (t >= off) ? ss[t - off] : 0u;
            __syncthreads();
            ss[t] += v;
            __syncthreads();
        }
        unsigned inc2 = ss[t];
        unsigned bef2 = inc2 - loc;
        if (r1 > bef2 && r1 <= inc2) {
            unsigned run = bef2;
            #pragma unroll
            for (int j = 0; j < 8; j++) {
                if (r1 <= run + p[j]) {
                    g_b2v = (unsigned)(t * 8 + j);
                    g_r2v = r1 - run;
                    break;
                }
                run += p[j];
            }
        }
        __syncthreads();
        if (t == 0) { __threadfence(); atomicExch(&g_rdy1, 1u); }
    }

    // ---- phase B: finalize mid>b2; stash mid==b2; 512-bin low hist ----
    if (t == 0) { while (atomicAdd(&g_rdy1, 0u) == 0u) {} }
    __syncthreads();
    unsigned b2 = g_b2v;
    bool stash_ovf = false;

    for (unsigned i = t; i < 512u; i += blockDim.x) sh[i] = 0u;
    __syncthreads();
    for (unsigned j = (unsigned)t; j < cnt; j += blockDim.x) {
        uint2 r = g_cand[region + j];
        if ((r.x >> 20) == b1) {
            unsigned mid = (r.x >> 9) & 2047u;
            if (mid > b2) out[r.y] = xs[r.y];
            else if (mid == b2) {
                agg_shared_add(sh, r.x & 511u);
                unsigned pos = atomicAdd(&s_stash, 1u);
                if (pos < STASH_MAX) stash[pos] = r;
                else stash_ovf = true;
            }
        }
    }
    __syncthreads();
    for (unsigned i = t; i < 512u; i += blockDim.x) {
        unsigned h = sh[i];
        if (h) atomicAdd(&g_hist_low[i], h);
    }
    __threadfence();
    __syncthreads();
    if (t == 0) atomicAdd(&g_d3, 1u);

    // ---- phase C2: block 0 selects exact threshold ----
    if (blockIdx.x == 0) {
        if (t == 0) { while (atomicAdd(&g_d3, 0u) < gridDim.x) {} }
        __syncthreads();
        unsigned r2 = g_r2v;
        unsigned q[2];
        unsigned loc = 0u;
        #pragma unroll
        for (int j = 0; j < 2; j++) { q[j] = g_hist_low[t * 2 + j]; loc += q[j]; }
        ss[t] = loc;
        __syncthreads();
        for (int off = 1; off < NTHREADS; off <<= 1) {
            unsigned v = (t >= off) ? ss[t - off] : 0u;
            __syncthreads();
            ss[t] += v;
            __syncthreads();
        }
        unsigned inc3 = ss[t];
        unsigned bef3 = inc3 - loc;
        if (r2 > bef3 && r2 <= inc3) {
            unsigned run = bef3;
            #pragma unroll
            for (int j = 0; j < 2; j++) {
                if (r2 <= run + q[j]) {
                    g_thr_key = (b1 << 20) | (b2 << 9) | (unsigned)(t * 2 + j);
                    break;
                }
                run += q[j];
            }
        }
        __syncthreads();
        if (t == 0) { __threadfence(); atomicExch(&g_rdy2, 1u); }
    }

    // ---- phase D: apply thr to stashed mid==b2 cands ----
    if (t == 0) { while (atomicAdd(&g_rdy2, 0u) == 0u) {} }
    __syncthreads();
    unsigned thr = g_thr_key;
    unsigned nst = s_stash;
    if (!stash_ovf && nst <= STASH_MAX) {
        for (unsigned j = (unsigned)t; j < nst; j += blockDim.x) {
            uint2 r = stash[j];
            if (r.x >= thr) out[r.y] = xs[r.y];
        }
    } else {
        // rare: re-stream region
        for (unsigned j = (unsigned)t; j < cnt; j += blockDim.x) {
            uint2 r = g_cand[region + j];
            if ((r.x >> 20) == b1 && ((r.x >> 9) & 2047u) == b2 && r.x >= thr)
                out[r.y] = xs[r.y];
        }
    }
}

// ---------------------------------------------------------------------------
extern "C" void kernel_launch(void* const* d_in, const int* in_sizes, int n_in,
                              void* d_out, int out_size) {
    const float* xs = (const float*)d_in[0];
    const float* ms = (const float*)d_in[1];
    const float* sp = (const float*)d_in[2];
    // d_in[3] = mask (unused by the reference computation)
    const int* t_ptr = (n_in >= 5) ? (const int*)d_in[4] : nullptr;

    unsigned n = (unsigned)in_sizes[0];
    float* out = (float*)d_out;

    zero_kernel<<<4, 1024>>>();
    sample_kernel<<<264, 256>>>(xs, ms, t_ptr, sp, n);
    passA_kernel<<<NBLOCKS, NTHREADS>>>(xs, ms, t_ptr, out, n);
    resolve_kernel<<<NBLOCKS, NTHREADS>>>(xs, ms, t_ptr, sp, out, n);
}

// round 8
// speedup vs baseline: 6.7118x; 1.1180x over previous
#include <cuda_runtime.h>
#include <stdint.h>

// ---------------------------------------------------------------------------
// MagnitudePruning via 2-level-sampled key-window radix select on
// s = t*magnitude + |x|  (monotone surrogate; uniform divide preserves rank).
//
// zero    : clear small histograms/counters
// sample  : persistent 2-phase: coarse 4096-bin hist -> coarse window
//           (<=16 top-12 bins) -> runtime shift fs -> fine 4096-bin hist
//           over window (samples L2-hot) -> exact key window [k_lo,k_hi)
// passA   : ONE full fused pass: exact below-count (key<k_lo), final out for
//           out-of-window, compact window cands (~300K) to per-block regions,
//           2048-bin fine whist
// resolve : persistent: select fine bin b1+r1; ONE region stream (finalize
//           key>=b1_end, stash+low-hist b1 cands); block0 -> exact thr;
//           apply from stash.  Exact single-block fallback on any miss.
// ---------------------------------------------------------------------------

#define NBLOCKS    1184u
#define NTHREADS   256u
#define TILE_F4    512u
#define PER_BLOCK  40960u
#define STASH_MAX  512u

__device__ unsigned g_coarse[4096];
__device__ unsigned g_fine[4096];
__device__ unsigned g_whist[2048];
__device__ unsigned g_lowh[4096];
__device__ unsigned g_below;
__device__ unsigned g_done1, g_done2, g_d2;
__device__ unsigned g_s2r, g_rdy2;
__device__ unsigned g_ovf;
__device__ unsigned g_wbase, g_fs, g_tlo, g_thi;
__device__ unsigned g_klo, g_khi;
__device__ unsigned g_thr_key;
__device__ unsigned g_blk_cnt[NBLOCKS];
__device__ uint2    g_cand[NBLOCKS * PER_BLOCK];

__device__ __forceinline__ unsigned key_of(float x, float m, float tf) {
    float s = __fadd_rn(__fmul_rn(tf, m), fabsf(x));
    return __float_as_uint(s);
}
__device__ __forceinline__ float read_tf(const int* t_ptr) {
    return t_ptr ? (float)(*t_ptr) : 1.0f;
}
__device__ __forceinline__ unsigned rank_R(const float* sp, unsigned n) {
    float fidx = floorf(__fsub_rn(__fmul_rn(sp[0], (float)n), 1.0f));
    long long idx = (long long)fidx;
    if (idx < 0) idx = 0;
    if (idx > (long long)(n - 1)) idx = (long long)(n - 1);
    return (unsigned)idx + 1u;
}
__device__ __forceinline__ void agg_shared_add(unsigned* hist, unsigned bin) {
    unsigned act    = __activemask();
    unsigned peers  = __match_any_sync(act, bin);
    int      leader = __ffs(peers) - 1;
    if ((int)(threadIdx.x & 31) == leader)
        atomicAdd(&hist[bin], (unsigned)__popc(peers));
}

// ---------------------------------------------------------------------------
__global__ void zero_kernel() {
    unsigned tid = blockIdx.x * blockDim.x + threadIdx.x;
    unsigned stride = gridDim.x * blockDim.x;
    for (unsigned i = tid; i < 4096u; i += stride) { g_coarse[i] = 0u; g_fine[i] = 0u; g_lowh[i] = 0u; }
    for (unsigned i = tid; i < 2048u; i += stride) g_whist[i] = 0u;
    if (tid == 0) {
        g_below = 0u; g_done1 = 0u; g_done2 = 0u; g_d2 = 0u;
        g_s2r = 0u; g_rdy2 = 0u; g_ovf = 0u;
    }
}

// ---------------------------------------------------------------------------
// Persistent 2-phase sampling kernel. 264 blocks (all resident).
__global__ void __launch_bounds__(NTHREADS, 2)
sample_kernel(const float* __restrict__ xs,
              const float* __restrict__ ms,
              const int* __restrict__ t_ptr,
              const float* __restrict__ sparsity,
              unsigned n) {
    __shared__ unsigned sh[4096];
    __shared__ unsigned sscan[256];
    __shared__ unsigned svlo, svhi, svS;
    for (unsigned i = threadIdx.x; i < 4096u; i += blockDim.x) sh[i] = 0u;
    __syncthreads();

    float tf = read_tf(t_ptr);
    unsigned n4 = n >> 2;
    unsigned stride4 = n4 / 262144u; if (stride4 == 0u) stride4 = 1u;
    unsigned nsamp4  = n4 / stride4;
    const float4* x4 = (const float4*)xs;
    const float4* m4 = (const float4*)ms;
    unsigned gstride = gridDim.x * blockDim.x;
    int t = threadIdx.x;

    // ---- phase 1: coarse hist (top 12 bits) ----
    for (unsigned i = blockIdx.x * blockDim.x + t; i < nsamp4; i += gstride) {
        unsigned idx = i * stride4;
        float4 xv = x4[idx];
        float4 mv = m4[idx];
        agg_shared_add(sh, key_of(xv.x, mv.x, tf) >> 20);
        agg_shared_add(sh, key_of(xv.y, mv.y, tf) >> 20);
        agg_shared_add(sh, key_of(xv.z, mv.z, tf) >> 20);
        agg_shared_add(sh, key_of(xv.w, mv.w, tf) >> 20);
    }
    __syncthreads();
    for (unsigned i = t; i < 4096u; i += blockDim.x) {
        unsigned c = sh[i];
        if (c) atomicAdd(&g_coarse[i], c);
    }
    __threadfence();

    __shared__ unsigned slast;
    if (t == 0)
        slast = (atomicAdd(&g_done1, 1u) == gridDim.x - 1u) ? 1u : 0u;
    __syncthreads();

    unsigned R = rank_R(sparsity, n);

    if (slast) {
        // coarse window from sampled ranks +-0.3%
        unsigned loc[16];
        unsigned lsum = 0u;
        #pragma unroll
        for (int j = 0; j < 16; j++) { loc[j] = g_coarse[t * 16 + j]; lsum += loc[j]; }
        sscan[t] = lsum;
        __syncthreads();
        for (int off = 1; off < 256; off <<= 1) {
            unsigned v = (t >= off) ? sscan[t - off] : 0u;
            __syncthreads();
            sscan[t] += v;
            __syncthreads();
        }
        unsigned incl  = sscan[t];
        unsigned total = sscan[255];
        unsigned before = incl - lsum;

        float f = (float)R / (float)n;
        float tlo = (f - 0.003f) * (float)total;
        float thi = (f + 0.003f) * (float)total + 1.0f;
        unsigned slo = (tlo < 1.0f) ? 1u : (unsigned)tlo;
        if (slo > total) slo = total;
        unsigned shi = (thi < 1.0f) ? 1u : (unsigned)thi;
        if (shi > total) shi = total;
        if (shi < slo) shi = slo;

        if (slo > before && slo <= incl) {
            unsigned run = before;
            #pragma unroll
            for (int j = 0; j < 16; j++) {
                if (slo <= run + loc[j]) { svlo = (unsigned)(t * 16 + j); svS = run; break; }
                run += loc[j];
            }
        }
        if (shi > before && shi <= incl) {
            unsigned run = before;
            #pragma unroll
            for (int j = 0; j < 16; j++) {
                if (shi <= run + loc[j]) { svhi = (unsigned)(t * 16 + j); break; }
                run += loc[j];
            }
        }
        __syncthreads();
        if (t == 0) {
            unsigned blo = svlo, bhi = svhi;
            if (bhi < blo) bhi = blo;
            if (bhi - blo + 1u > 16u) bhi = blo + 15u;
            unsigned span = bhi - blo + 1u;
            unsigned fs = 8u;
            while ((((unsigned long long)span << 20) >> fs) > 4096ull) fs++;
            g_wbase = blo << 20;
            g_fs = fs;
            g_tlo = slo - svS;
            g_thi = (shi > svS) ? (shi - svS) : 1u;
            __threadfence();
            atomicExch(&g_s2r, 1u);
        }
    }

    // ---- phase 2: fine hist over window (samples are L2-hot) ----
    if (t == 0) { while (atomicAdd(&g_s2r, 0u) == 0u) {} }
    __syncthreads();
    unsigned wbase = g_wbase;
    unsigned fs    = g_fs;

    for (unsigned i = t; i < 4096u; i += blockDim.x) sh[i] = 0u;
    __syncthreads();
    for (unsigned i = blockIdx.x * blockDim.x + t; i < nsamp4; i += gstride) {
        unsigned idx = i * stride4;
        float4 xv = x4[idx];
        float4 mv = m4[idx];
        unsigned kk[4];
        kk[0] = key_of(xv.x, mv.x, tf);
        kk[1] = key_of(xv.y, mv.y, tf);
        kk[2] = key_of(xv.z, mv.z, tf);
        kk[3] = key_of(xv.w, mv.w, tf);
        #pragma unroll
        for (int j = 0; j < 4; j++) {
            if (kk[j] >= wbase) {
                unsigned b = (kk[j] - wbase) >> fs;
                if (b < 4096u) agg_shared_add(sh, b);
            }
        }
    }
    __syncthreads();
    for (unsigned i = t; i < 4096u; i += blockDim.x) {
        unsigned c = sh[i];
        if (c) atomicAdd(&g_fine[i], c);
    }
    __threadfence();

    __shared__ unsigned slast2;
    if (t == 0)
        slast2 = (atomicAdd(&g_done2, 1u) == gridDim.x - 1u) ? 1u : 0u;
    __syncthreads();
    if (!slast2) return;

    // ---- last block: fine window -> exact key bounds ----
    {
        unsigned loc[16];
        unsigned lsum = 0u;
        #pragma unroll
        for (int j = 0; j < 16; j++) { loc[j] = g_fine[t * 16 + j]; lsum += loc[j]; }
        sscan[t] = lsum;
        __syncthreads();
        for (int off = 1; off < 256; off <<= 1) {
            unsigned v = (t >= off) ? sscan[t - off] : 0u;
            __syncthreads();
            sscan[t] += v;
            __syncthreads();
        }
        unsigned incl  = sscan[t];
        unsigned total = sscan[255];
        unsigned before = incl - lsum;

        if (t == 0) { svlo = 0u; svhi = 2047u; }
        __syncthreads();

        if (total > 0u) {
            unsigned tl = g_tlo; if (tl < 1u) tl = 1u; if (tl > total) tl = total;
            unsigned th = g_thi; if (th < tl) th = tl; if (th > total) th = total;
            if (tl > before && tl <= incl) {
                unsigned run = before;
                #pragma unroll
                for (int j = 0; j < 16; j++) {
                    if (tl <= run + loc[j]) { svlo = (unsigned)(t * 16 + j); break; }
                    run += loc[j];
                }
            }
            if (th > before && th <= incl) {
                unsigned run = before;
                #pragma unroll
                for (int j = 0; j < 16; j++) {
                    if (th <= run + loc[j]) { svhi = (unsigned)(t * 16 + j); break; }
                    run += loc[j];
                }
            }
        }
        __syncthreads();
        if (t == 0) {
            unsigned flo = svlo, fhi = svhi;
            if (fhi < flo) fhi = flo;
            if (fhi - flo > 2047u) fhi = flo + 2047u;
            g_klo = wbase + (flo << fs);
            g_khi = wbase + ((fhi + 1u) << fs);
        }
    }
}

// ---------------------------------------------------------------------------
// The single fused full pass over all data.
__global__ void __launch_bounds__(NTHREADS, 8)
passA_kernel(const float* __restrict__ xs,
             const float* __restrict__ ms,
             const int* __restrict__ t_ptr,
             float* __restrict__ out,
             unsigned n) {
    __shared__ uint2    s_buf[2048];
    __shared__ unsigned s_whist[2048];
    __shared__ unsigned s_cnt;
    __shared__ unsigned s_red[NTHREADS];

    for (unsigned i = threadIdx.x; i < 2048u; i += blockDim.x) s_whist[i] = 0u;

    float tf = read_tf(t_ptr);
    unsigned k_lo = g_klo, k_hi = g_khi;
    unsigned fs = g_fs;
    unsigned n4 = n >> 2;
    const float4* x4 = (const float4*)xs;
    const float4* m4 = (const float4*)ms;
    float4* o4 = (float4*)out;

    unsigned region = blockIdx.x * PER_BLOCK;
    unsigned nreg = 0u;
    unsigned below = 0u;
    unsigned ntiles = (n4 + TILE_F4 - 1u) / TILE_F4;

    for (unsigned tile = blockIdx.x; tile < ntiles; tile += gridDim.x) {
        if (threadIdx.x == 0) s_cnt = 0u;
        __syncthreads();

        unsigned tbase = tile * TILE_F4;
        #pragma unroll
        for (int k = 0; k < 2; k++) {
            unsigned i = tbase + (unsigned)k * NTHREADS + threadIdx.x;
            if (i < n4) {
                float4 xv = x4[i];
                float4 mv = m4[i];
                unsigned e = i * 4u;
                unsigned kk[4];
                kk[0] = key_of(xv.x, mv.x, tf);
                kk[1] = key_of(xv.y, mv.y, tf);
                kk[2] = key_of(xv.z, mv.z, tf);
                kk[3] = key_of(xv.w, mv.w, tf);
                float vv[4] = {xv.x, xv.y, xv.z, xv.w};
                float ov[4];
                #pragma unroll
                for (int j = 0; j < 4; j++) {
                    unsigned key = kk[j];
                    below += (key < k_lo) ? 1u : 0u;
                    ov[j] = (key >= k_hi) ? vv[j] : 0.0f;
                    if (key >= k_lo && key < k_hi) {
                        unsigned pos = atomicAdd(&s_cnt, 1u);
                        s_buf[pos] = make_uint2(key, e + (unsigned)j);
                        agg_shared_add(s_whist, (key - k_lo) >> fs);
                    }
                }
                o4[i] = make_float4(ov[0], ov[1], ov[2], ov[3]);
            }
        }
        __syncthreads();

        unsigned cnt = s_cnt;
        if (cnt) {
            if (nreg + cnt <= PER_BLOCK) {
                for (unsigned j = threadIdx.x; j < cnt; j += blockDim.x)
                    g_cand[region + nreg + j] = s_buf[j];
                nreg += cnt;
            } else {
                if (threadIdx.x == 0) atomicExch(&g_ovf, 1u);
            }
        }
        __syncthreads();
    }

    // scalar tail (n % 4)
    if (blockIdx.x == 0 && threadIdx.x == 0) {
        for (unsigned i = n4 << 2; i < n; i++) {
            unsigned key = key_of(xs[i], ms[i], tf);
            below += (key < k_lo) ? 1u : 0u;
            out[i] = (key >= k_hi) ? xs[i] : 0.0f;
            if (key >= k_lo && key < k_hi) {
                if (nreg < PER_BLOCK) {
                    g_cand[region + nreg] = make_uint2(key, i);
                    nreg++;
                    atomicAdd(&s_whist[(key - k_lo) >> fs], 1u);
                } else {
                    atomicExch(&g_ovf, 1u);
                }
            }
        }
    }
    __syncthreads();

    if (threadIdx.x == 0) g_blk_cnt[blockIdx.x] = nreg;

    s_red[threadIdx.x] = below;
    __syncthreads();
    for (int off = NTHREADS / 2; off > 0; off >>= 1) {
        if ((int)threadIdx.x < off) s_red[threadIdx.x] += s_red[threadIdx.x + off];
        __syncthreads();
    }
    if (threadIdx.x == 0 && s_red[0]) atomicAdd(&g_below, s_red[0]);

    for (unsigned i = threadIdx.x; i < 2048u; i += blockDim.x) {
        unsigned c = s_whist[i];
        if (c) atomicAdd(&g_whist[i], c);
    }
}

// ---------------------------------------------------------------------------
// Persistent tail: one region stream + one grid barrier.
__global__ void __launch_bounds__(NTHREADS, 8)
resolve_kernel(const float* __restrict__ xs,
               const float* __restrict__ ms,
               const int* __restrict__ t_ptr,
               const float* __restrict__ sparsity,
               float* __restrict__ out,
               unsigned n) {
    __shared__ unsigned ss[NTHREADS];
    __shared__ unsigned sh[4096];
    __shared__ uint2    stash[STASH_MAX];
    __shared__ unsigned sb1, sr1, s_stash;
    __shared__ unsigned sv[4];
    int t = threadIdx.x;

    // ---- select fine bin b1 + r1 from g_whist + g_below ----
    if (t == 0) { sb1 = 0xFFFFFFFFu; sr1 = 1u; s_stash = 0u; }
    unsigned c[8];
    unsigned local = 0u;
    #pragma unroll
    for (int j = 0; j < 8; j++) { c[j] = g_whist[t * 8 + j]; local += c[j]; }
    ss[t] = local;
    __syncthreads();
    for (int off = 1; off < NTHREADS; off <<= 1) {
        unsigned v = (t >= off) ? ss[t - off] : 0u;
        __syncthreads();
        ss[t] += v;
        __syncthreads();
    }
    unsigned incl   = ss[t];
    unsigned total  = ss[NTHREADS - 1];
    unsigned before = incl - local;

    unsigned below = g_below;
    unsigned R = rank_R(sparsity, n);
    bool fb = (below >= R) || ((R - below) > total) || (g_ovf != 0u);
    unsigned Rp = R - below;

    if (!fb && Rp > before && Rp <= incl) {
        unsigned run = before;
        #pragma unroll
        for (int j = 0; j < 8; j++) {
            if (Rp <= run + c[j]) {
                sb1 = (unsigned)(t * 8 + j);
                sr1 = Rp - run;
                break;
            }
            run += c[j];
        }
    }
    __syncthreads();

    // ---- fallback: block 0 exact 3-level radix over full data ----
    if (fb) {
        if (blockIdx.x != 0) return;
        float tf = read_tf(t_ptr);

        for (unsigned i = t; i < 4096u; i += blockDim.x) sh[i] = 0u;
        __syncthreads();
        for (unsigned i = t; i < n; i += blockDim.x)
            atomicAdd(&sh[key_of(xs[i], ms[i], tf) >> 20], 1u);
        __syncthreads();
        if (t == 0) {
            unsigned run = 0u;
            for (unsigned b = 0; b < 4096u; b++) {
                if (R <= run + sh[b]) { sv[0] = b; sv[1] = R - run; break; }
                run += sh[b];
            }
        }
        __syncthreads();
        unsigned b1 = sv[0], r1 = sv[1];

        for (unsigned i = t; i < 1024u; i += blockDim.x) sh[i] = 0u;
        __syncthreads();
        for (unsigned i = t; i < n; i += blockDim.x) {
            unsigned k = key_of(xs[i], ms[i], tf);
            if ((k >> 20) == b1) atomicAdd(&sh[(k >> 10) & 1023u], 1u);
        }
        __syncthreads();
        if (t == 0) {
            unsigned run = 0u;
            for (unsigned b = 0; b < 1024u; b++) {
                if (r1 <= run + sh[b]) { sv[2] = b; sv[1] = r1 - run; break; }
                run += sh[b];
            }
        }
        __syncthreads();
        unsigned b2 = sv[2], r2 = sv[1];
        unsigned pre = (b1 << 10) | b2;

        for (unsigned i = t; i < 1024u; i += blockDim.x) sh[i] = 0u;
        __syncthreads();
        for (unsigned i = t; i < n; i += blockDim.x) {
            unsigned k = key_of(xs[i], ms[i], tf);
            if ((k >> 10) == pre) atomicAdd(&sh[k & 1023u], 1u);
        }
        __syncthreads();
        if (t == 0) {
            unsigned run = 0u;
            for (unsigned b = 0; b < 1024u; b++) {
                if (r2 <= run + sh[b]) { sv[3] = (pre << 10) | b; break; }
                run += sh[b];
            }
        }
        __syncthreads();
        unsigned thr = sv[3];
        for (unsigned i = t; i < n; i += blockDim.x) {
            unsigned k = key_of(xs[i], ms[i], tf);
            out[i] = (k >= thr) ? xs[i] : 0.0f;
        }
        return;
    }

    unsigned b1 = sb1;
    unsigned r1 = sr1;
    unsigned k_lo = g_klo;
    unsigned fs   = g_fs;
    unsigned nlow = 1u << fs;                      // <= 4096
    unsigned b1start = k_lo + (b1 << fs);
    unsigned b1end   = b1start + (1u << fs);
    unsigned lowmask = nlow - 1u;
    unsigned cnt    = g_blk_cnt[blockIdx.x];
    unsigned region = blockIdx.x * PER_BLOCK;

    // ---- phase A: single region stream ----
    for (unsigned i = t; i < nlow; i += blockDim.x) sh[i] = 0u;
    __syncthreads();
    for (unsigned j = (unsigned)t; j < cnt; j += blockDim.x) {
        uint2 r = g_cand[region + j];
        if (r.x >= b1end) out[r.y] = xs[r.y];
        else if (r.x >= b1start) {
            agg_shared_add(sh, r.x & lowmask);
            unsigned pos = atomicAdd(&s_stash, 1u);
            if (pos < STASH_MAX) stash[pos] = r;
        }
    }
    __syncthreads();
    for (unsigned i = t; i < nlow; i += blockDim.x) {
        unsigned h = sh[i];
        if (h) atomicAdd(&g_lowh[i], h);
    }
    __threadfence();
    __syncthreads();
    if (t == 0) atomicAdd(&g_d2, 1u);

    // ---- block 0: exact threshold from low hist ----
    if (blockIdx.x == 0) {
        if (t == 0) { while (atomicAdd(&g_d2, 0u) < gridDim.x) {} }
        __syncthreads();
        unsigned q[16];
        unsigned loc = 0u;
        #pragma unroll
        for (int j = 0; j < 16; j++) { q[j] = g_lowh[t * 16 + j]; loc += q[j]; }
        ss[t] = loc;
        __syncthreads();
        for (int off = 1; off < NTHREADS; off <<= 1) {
            unsigned v = (t >= off) ? ss[t - off] : 0u;
            __syncthreads();
            ss[t] += v;
            __syncthreads();
        }
        unsigned inc3 = ss[t];
        unsigned bef3 = inc3 - loc;
        if (r1 > bef3 && r1 <= inc3) {
            unsigned run = bef3;
            #pragma unroll
            for (int j = 0; j < 16; j++) {
                if (r1 <= run + q[j]) {
                    g_thr_key = b1start + (unsigned)(t * 16 + j);
                    break;
                }
                run += q[j];
            }
        }
        __syncthreads();
        if (t == 0) { __threadfence(); atomicExch(&g_rdy2, 1u); }
    }

    // ---- apply thr to stashed b1 cands ----
    if (t == 0) { while (atomicAdd(&g_rdy2, 0u) == 0u) {} }
    __syncthreads();
    unsigned thr = g_thr_key;
    unsigned nst = s_stash;
    if (nst <= STASH_MAX) {
        for (unsigned j = (unsigned)t; j < nst; j += blockDim.x) {
            uint2 r = stash[j];
            if (r.x >= thr) out[r.y] = xs[r.y];
        }
    } else {
        for (unsigned j = (unsigned)t; j < cnt; j += blockDim.x) {
            uint2 r = g_cand[region + j];
            if (r.x >= thr && r.x < b1end) out[r.y] = xs[r.y];
        }
    }
}

// ---------------------------------------------------------------------------
extern "C" void kernel_launch(void* const* d_in, const int* in_sizes, int n_in,
                              void* d_out, int out_size) {
    const float* xs = (const float*)d_in[0];
    const float* ms = (const float*)d_in[1];
    const float* sp = (const float*)d_in[2];
    // d_in[3] = mask (unused by the reference computation)
    const int* t_ptr = (n_in >= 5) ? (const int*)d_in[4] : nullptr;

    unsigned n = (unsigned)in_sizes[0];
    float* out = (float*)d_out;

    zero_kernel<<<4, 1024>>>();
    sample_kernel<<<264, 256>>>(xs, ms, t_ptr, sp, n);
    passA_kernel<<<NBLOCKS, NTHREADS>>>(xs, ms, t_ptr, out, n);
    resolve_kernel<<<NBLOCKS, NTHREADS>>>(xs, ms, t_ptr, sp, out, n);
}

// round 9
// speedup vs baseline: 7.1117x; 1.0596x over previous
#include <cuda_runtime.h>
#include <stdint.h>

// ---------------------------------------------------------------------------
// MagnitudePruning via 2-level-sampled key-window radix select on
// s = t*magnitude + |x|  (monotone surrogate; uniform divide preserves rank).
//
// zero    : clear small histograms/counters
// sample  : persistent 2-phase, CHUNKED coalesced sampling (2048 chunks x
//           512 elems = 1M samples): coarse 4096-bin hist -> coarse window
//           -> runtime shift fs -> fine 4096-bin hist (samples L2-hot)
//           -> exact key window [k_lo,k_hi)
// passA   : ONE full fused pass (streaming hints): exact below-count,
//           final out for out-of-window, compact window cands to per-block
//           regions, 2048-bin fine whist
// resolve : persistent: select fine bin b1+r1; ONE region stream (finalize
//           key>=b1_end, stash+low-hist b1 cands); block0 -> exact thr;
//           apply from stash.  Exact single-block fallback on any miss.
// ---------------------------------------------------------------------------

#define NBLOCKS    1184u
#define NTHREADS   256u
#define TILE_F4    512u
#define PER_BLOCK  40960u
#define STASH_MAX  512u
#define NCHUNKS    2048u
#define CHUNK_F4   128u

__device__ unsigned g_coarse[4096];
__device__ unsigned g_fine[4096];
__device__ unsigned g_whist[2048];
__device__ unsigned g_lowh[4096];
__device__ unsigned g_below;
__device__ unsigned g_done1, g_done2, g_d2;
__device__ unsigned g_s2r, g_rdy2;
__device__ unsigned g_ovf;
__device__ unsigned g_wbase, g_fs, g_tlo, g_thi;
__device__ unsigned g_klo, g_khi;
__device__ unsigned g_thr_key;
__device__ unsigned g_blk_cnt[NBLOCKS];
__device__ uint2    g_cand[NBLOCKS * PER_BLOCK];

__device__ __forceinline__ unsigned key_of(float x, float m, float tf) {
    float s = __fadd_rn(__fmul_rn(tf, m), fabsf(x));
    return __float_as_uint(s);
}
__device__ __forceinline__ float read_tf(const int* t_ptr) {
    return t_ptr ? (float)(*t_ptr) : 1.0f;
}
__device__ __forceinline__ unsigned rank_R(const float* sp, unsigned n) {
    float fidx = floorf(__fsub_rn(__fmul_rn(sp[0], (float)n), 1.0f));
    long long idx = (long long)fidx;
    if (idx < 0) idx = 0;
    if (idx > (long long)(n - 1)) idx = (long long)(n - 1);
    return (unsigned)idx + 1u;
}
__device__ __forceinline__ void agg_shared_add(unsigned* hist, unsigned bin) {
    unsigned act    = __activemask();
    unsigned peers  = __match_any_sync(act, bin);
    int      leader = __ffs(peers) - 1;
    if ((int)(threadIdx.x & 31) == leader)
        atomicAdd(&hist[bin], (unsigned)__popc(peers));
}

// ---------------------------------------------------------------------------
__global__ void zero_kernel() {
    unsigned tid = blockIdx.x * blockDim.x + threadIdx.x;
    unsigned stride = gridDim.x * blockDim.x;
    for (unsigned i = tid; i < 4096u; i += stride) { g_coarse[i] = 0u; g_fine[i] = 0u; g_lowh[i] = 0u; }
    for (unsigned i = tid; i < 2048u; i += stride) g_whist[i] = 0u;
    if (tid == 0) {
        g_below = 0u; g_done1 = 0u; g_done2 = 0u; g_d2 = 0u;
        g_s2r = 0u; g_rdy2 = 0u; g_ovf = 0u;
    }
}

// ---------------------------------------------------------------------------
// Persistent 2-phase sampling kernel. 264 blocks (all resident).
// Chunked sampling: sample index i -> chunk (i>>7), offset (i&127);
// chunk c starts at (c * n4) / NCHUNKS float4s. Fully coalesced.
__global__ void __launch_bounds__(NTHREADS, 2)
sample_kernel(const float* __restrict__ xs,
              const float* __restrict__ ms,
              const int* __restrict__ t_ptr,
              const float* __restrict__ sparsity,
              unsigned n) {
    __shared__ unsigned sh[4096];
    __shared__ unsigned sscan[256];
    __shared__ unsigned svlo, svhi, svS;
    for (unsigned i = threadIdx.x; i < 4096u; i += blockDim.x) sh[i] = 0u;
    __syncthreads();

    float tf = read_tf(t_ptr);
    unsigned n4 = n >> 2;
    unsigned nsamp4 = NCHUNKS * CHUNK_F4;
    bool small = (n4 < nsamp4);
    const float4* x4 = (const float4*)xs;
    const float4* m4 = (const float4*)ms;
    unsigned gstride = gridDim.x * blockDim.x;
    int t = threadIdx.x;
    if (small) nsamp4 = n4;

    // ---- phase 1: coarse hist (top 12 bits) ----
    for (unsigned i = blockIdx.x * blockDim.x + t; i < nsamp4; i += gstride) {
        unsigned idx;
        if (small) idx = i;
        else {
            unsigned chunk = i >> 7;
            unsigned off   = i & (CHUNK_F4 - 1u);
            idx = (unsigned)(((unsigned long long)chunk * n4) / NCHUNKS) + off;
        }
        float4 xv = x4[idx];
        float4 mv = m4[idx];
        agg_shared_add(sh, key_of(xv.x, mv.x, tf) >> 20);
        agg_shared_add(sh, key_of(xv.y, mv.y, tf) >> 20);
        agg_shared_add(sh, key_of(xv.z, mv.z, tf) >> 20);
        agg_shared_add(sh, key_of(xv.w, mv.w, tf) >> 20);
    }
    __syncthreads();
    for (unsigned i = t; i < 4096u; i += blockDim.x) {
        unsigned c = sh[i];
        if (c) atomicAdd(&g_coarse[i], c);
    }
    __threadfence();

    __shared__ unsigned slast;
    if (t == 0)
        slast = (atomicAdd(&g_done1, 1u) == gridDim.x - 1u) ? 1u : 0u;
    __syncthreads();

    unsigned R = rank_R(sparsity, n);

    if (slast) {
        // coarse window from sampled ranks +-0.3%
        unsigned loc[16];
        unsigned lsum = 0u;
        #pragma unroll
        for (int j = 0; j < 16; j++) { loc[j] = g_coarse[t * 16 + j]; lsum += loc[j]; }
        sscan[t] = lsum;
        __syncthreads();
        for (int off = 1; off < 256; off <<= 1) {
            unsigned v = (t >= off) ? sscan[t - off] : 0u;
            __syncthreads();
            sscan[t] += v;
            __syncthreads();
        }
        unsigned incl  = sscan[t];
        unsigned total = sscan[255];
        unsigned before = incl - lsum;

        float f = (float)R / (float)n;
        float tlo = (f - 0.003f) * (float)total;
        float thi = (f + 0.003f) * (float)total + 1.0f;
        unsigned slo = (tlo < 1.0f) ? 1u : (unsigned)tlo;
        if (slo > total) slo = total;
        unsigned shi = (thi < 1.0f) ? 1u : (unsigned)thi;
        if (shi > total) shi = total;
        if (shi < slo) shi = slo;

        if (slo > before && slo <= incl) {
            unsigned run = before;
            #pragma unroll
            for (int j = 0; j < 16; j++) {
                if (slo <= run + loc[j]) { svlo = (unsigned)(t * 16 + j); svS = run; break; }
                run += loc[j];
            }
        }
        if (shi > before && shi <= incl) {
            unsigned run = before;
            #pragma unroll
            for (int j = 0; j < 16; j++) {
                if (shi <= run + loc[j]) { svhi = (unsigned)(t * 16 + j); break; }
                run += loc[j];
            }
        }
        __syncthreads();
        if (t == 0) {
            unsigned blo = svlo, bhi = svhi;
            if (bhi < blo) bhi = blo;
            if (bhi - blo + 1u > 16u) bhi = blo + 15u;
            unsigned span = bhi - blo + 1u;
            unsigned fs = 8u;
            while ((((unsigned long long)span << 20) >> fs) > 4096ull) fs++;
            g_wbase = blo << 20;
            g_fs = fs;
            g_tlo = slo - svS;
            g_thi = (shi > svS) ? (shi - svS) : 1u;
            __threadfence();
            atomicExch(&g_s2r, 1u);
        }
    }

    // ---- phase 2: fine hist over window (samples L2-hot) ----
    if (t == 0) { while (atomicAdd(&g_s2r, 0u) == 0u) {} }
    __syncthreads();
    unsigned wbase = g_wbase;
    unsigned fs    = g_fs;

    for (unsigned i = t; i < 4096u; i += blockDim.x) sh[i] = 0u;
    __syncthreads();
    for (unsigned i = blockIdx.x * blockDim.x + t; i < nsamp4; i += gstride) {
        unsigned idx;
        if (small) idx = i;
        else {
            unsigned chunk = i >> 7;
            unsigned off   = i & (CHUNK_F4 - 1u);
            idx = (unsigned)(((unsigned long long)chunk * n4) / NCHUNKS) + off;
        }
        float4 xv = x4[idx];
        float4 mv = m4[idx];
        unsigned kk[4];
        kk[0] = key_of(xv.x, mv.x, tf);
        kk[1] = key_of(xv.y, mv.y, tf);
        kk[2] = key_of(xv.z, mv.z, tf);
        kk[3] = key_of(xv.w, mv.w, tf);
        #pragma unroll
        for (int j = 0; j < 4; j++) {
            if (kk[j] >= wbase) {
                unsigned b = (kk[j] - wbase) >> fs;
                if (b < 4096u) agg_shared_add(sh, b);
            }
        }
    }
    __syncthreads();
    for (unsigned i = t; i < 4096u; i += blockDim.x) {
        unsigned c = sh[i];
        if (c) atomicAdd(&g_fine[i], c);
    }
    __threadfence();

    __shared__ unsigned slast2;
    if (t == 0)
        slast2 = (atomicAdd(&g_done2, 1u) == gridDim.x - 1u) ? 1u : 0u;
    __syncthreads();
    if (!slast2) return;

    // ---- last block: fine window -> exact key bounds ----
    {
        unsigned loc[16];
        unsigned lsum = 0u;
        #pragma unroll
        for (int j = 0; j < 16; j++) { loc[j] = g_fine[t * 16 + j]; lsum += loc[j]; }
        sscan[t] = lsum;
        __syncthreads();
        for (int off = 1; off < 256; off <<= 1) {
            unsigned v = (t >= off) ? sscan[t - off] : 0u;
            __syncthreads();
            sscan[t] += v;
            __syncthreads();
        }
        unsigned incl  = sscan[t];
        unsigned total = sscan[255];
        unsigned before = incl - lsum;

        if (t == 0) { svlo = 0u; svhi = 2047u; }
        __syncthreads();

        if (total > 0u) {
            unsigned tl = g_tlo; if (tl < 1u) tl = 1u; if (tl > total) tl = total;
            unsigned th = g_thi; if (th < tl) th = tl; if (th > total) th = total;
            if (tl > before && tl <= incl) {
                unsigned run = before;
                #pragma unroll
                for (int j = 0; j < 16; j++) {
                    if (tl <= run + loc[j]) { svlo = (unsigned)(t * 16 + j); break; }
                    run += loc[j];
                }
            }
            if (th > before && th <= incl) {
                unsigned run = before;
                #pragma unroll
                for (int j = 0; j < 16; j++) {
                    if (th <= run + loc[j]) { svhi = (unsigned)(t * 16 + j); break; }
                    run += loc[j];
                }
            }
        }
        __syncthreads();
        if (t == 0) {
            unsigned flo = svlo, fhi = svhi;
            if (fhi < flo) fhi = flo;
            if (fhi - flo > 2047u) fhi = flo + 2047u;
            g_klo = wbase + (flo << fs);
            g_khi = wbase + ((fhi + 1u) << fs);
        }
    }
}

// ---------------------------------------------------------------------------
// The single fused full pass over all data (streaming loads/stores).
__global__ void __launch_bounds__(NTHREADS, 8)
passA_kernel(const float* __restrict__ xs,
             const float* __restrict__ ms,
             const int* __restrict__ t_ptr,
             float* __restrict__ out,
             unsigned n) {
    __shared__ uint2    s_buf[2048];
    __shared__ unsigned s_whist[2048];
    __shared__ unsigned s_cnt;
    __shared__ unsigned s_red[NTHREADS];

    for (unsigned i = threadIdx.x; i < 2048u; i += blockDim.x) s_whist[i] = 0u;

    float tf = read_tf(t_ptr);
    unsigned k_lo = g_klo, k_hi = g_khi;
    unsigned fs = g_fs;
    unsigned n4 = n >> 2;
    const float4* x4 = (const float4*)xs;
    const float4* m4 = (const float4*)ms;
    float4* o4 = (float4*)out;

    unsigned region = blockIdx.x * PER_BLOCK;
    unsigned nreg = 0u;
    unsigned below = 0u;
    unsigned ntiles = (n4 + TILE_F4 - 1u) / TILE_F4;

    for (unsigned tile = blockIdx.x; tile < ntiles; tile += gridDim.x) {
        if (threadIdx.x == 0) s_cnt = 0u;
        __syncthreads();

        unsigned tbase = tile * TILE_F4;
        #pragma unroll
        for (int k = 0; k < 2; k++) {
            unsigned i = tbase + (unsigned)k * NTHREADS + threadIdx.x;
            if (i < n4) {
                float4 xv = __ldcs(&x4[i]);
                float4 mv = __ldcs(&m4[i]);
                unsigned e = i * 4u;
                unsigned kk[4];
                kk[0] = key_of(xv.x, mv.x, tf);
                kk[1] = key_of(xv.y, mv.y, tf);
                kk[2] = key_of(xv.z, mv.z, tf);
                kk[3] = key_of(xv.w, mv.w, tf);
                float vv[4] = {xv.x, xv.y, xv.z, xv.w};
                float ov[4];
                #pragma unroll
                for (int j = 0; j < 4; j++) {
                    unsigned key = kk[j];
                    below += (key < k_lo) ? 1u : 0u;
                    ov[j] = (key >= k_hi) ? vv[j] : 0.0f;
                    if (key >= k_lo && key < k_hi) {
                        unsigned pos = atomicAdd(&s_cnt, 1u);
                        s_buf[pos] = make_uint2(key, e + (unsigned)j);
                        agg_shared_add(s_whist, (key - k_lo) >> fs);
                    }
                }
                __stcs(&o4[i], make_float4(ov[0], ov[1], ov[2], ov[3]));
            }
        }
        __syncthreads();

        unsigned cnt = s_cnt;
        if (cnt) {
            if (nreg + cnt <= PER_BLOCK) {
                for (unsigned j = threadIdx.x; j < cnt; j += blockDim.x)
                    g_cand[region + nreg + j] = s_buf[j];
                nreg += cnt;
            } else {
                if (threadIdx.x == 0) atomicExch(&g_ovf, 1u);
            }
        }
        __syncthreads();
    }

    // scalar tail (n % 4)
    if (blockIdx.x == 0 && threadIdx.x == 0) {
        for (unsigned i = n4 << 2; i < n; i++) {
            unsigned key = key_of(xs[i], ms[i], tf);
            below += (key < k_lo) ? 1u : 0u;
            out[i] = (key >= k_hi) ? xs[i] : 0.0f;
            if (key >= k_lo && key < k_hi) {
                if (nreg < PER_BLOCK) {
                    g_cand[region + nreg] = make_uint2(key, i);
                    nreg++;
                    atomicAdd(&s_whist[(key - k_lo) >> fs], 1u);
                } else {
                    atomicExch(&g_ovf, 1u);
                }
            }
        }
    }
    __syncthreads();

    if (threadIdx.x == 0) g_blk_cnt[blockIdx.x] = nreg;

    s_red[threadIdx.x] = below;
    __syncthreads();
    for (int off = NTHREADS / 2; off > 0; off >>= 1) {
        if ((int)threadIdx.x < off) s_red[threadIdx.x] += s_red[threadIdx.x + off];
        __syncthreads();
    }
    if (threadIdx.x == 0 && s_red[0]) atomicAdd(&g_below, s_red[0]);

    for (unsigned i = threadIdx.x; i < 2048u; i += blockDim.x) {
        unsigned c = s_whist[i];
        if (c) atomicAdd(&g_whist[i], c);
    }
}

// ---------------------------------------------------------------------------
// Persistent tail: one region stream + one grid barrier.
__global__ void __launch_bounds__(NTHREADS, 8)
resolve_kernel(const float* __restrict__ xs,
               const float* __restrict__ ms,
               const int* __restrict__ t_ptr,
               const float* __restrict__ sparsity,
               float* __restrict__ out,
               unsigned n) {
    __shared__ unsigned ss[NTHREADS];
    __shared__ unsigned sh[4096];
    __shared__ uint2    stash[STASH_MAX];
    __shared__ unsigned sb1, sr1, s_stash;
    __shared__ unsigned sv[4];
    int t = threadIdx.x;

    // ---- select fine bin b1 + r1 from g_whist + g_below ----
    if (t == 0) { sb1 = 0xFFFFFFFFu; sr1 = 1u; s_stash = 0u; }
    unsigned c[8];
    unsigned local = 0u;
    #pragma unroll
    for (int j = 0; j < 8; j++) { c[j] = g_whist[t * 8 + j]; local += c[j]; }
    ss[t] = local;
    __syncthreads();
    for (int off = 1; off < NTHREADS; off <<= 1) {
        unsigned v = (t >= off) ? ss[t - off] : 0u;
        __syncthreads();
        ss[t] += v;
        __syncthreads();
    }
    unsigned incl   = ss[t];
    unsigned total  = ss[NTHREADS - 1];
    unsigned before = incl - local;

    unsigned below = g_below;
    unsigned R = rank_R(sparsity, n);
    bool fb = (below >= R) || ((R - below) > total) || (g_ovf != 0u);
    unsigned Rp = R - below;

    if (!fb && Rp > before && Rp <= incl) {
        unsigned run = before;
        #pragma unroll
        for (int j = 0; j < 8; j++) {
            if (Rp <= run + c[j]) {
                sb1 = (unsigned)(t * 8 + j);
                sr1 = Rp - run;
                break;
            }
            run += c[j];
        }
    }
    __syncthreads();

    // ---- fallback: block 0 exact 3-level radix over full data ----
    if (fb) {
        if (blockIdx.x != 0) return;
        float tf = read_tf(t_ptr);

        for (unsigned i = t; i < 4096u; i += blockDim.x) sh[i] = 0u;
        __syncthreads();
        for (unsigned i = t; i < n; i += blockDim.x)
            atomicAdd(&sh[key_of(xs[i], ms[i], tf) >> 20], 1u);
        __syncthreads();
        if (t == 0) {
            unsigned run = 0u;
            for (unsigned b = 0; b < 4096u; b++) {
                if (R <= run + sh[b]) { sv[0] = b; sv[1] = R - run; break; }
                run += sh[b];
            }
        }
        __syncthreads();
        unsigned b1 = sv[0], r1 = sv[1];

        for (unsigned i = t; i < 1024u; i += blockDim.x) sh[i] = 0u;
        __syncthreads();
        for (unsigned i = t; i < n; i += blockDim.x) {
            unsigned k = key_of(xs[i], ms[i], tf);
            if ((k >> 20) == b1) atomicAdd(&sh[(k >> 10) & 1023u], 1u);
        }
        __syncthreads();
        if (t == 0) {
            unsigned run = 0u;
            for (unsigned b = 0; b < 1024u; b++) {
                if (r1 <= run + sh[b]) { sv[2] = b; sv[1] = r1 - run; break; }
                run += sh[b];
            }
        }
        __syncthreads();
        unsigned b2 = sv[2], r2 = sv[1];
        unsigned pre = (b1 << 10) | b2;

        for (unsigned i = t; i < 1024u; i += blockDim.x) sh[i] = 0u;
        __syncthreads();
        for (unsigned i = t; i < n; i += blockDim.x) {
            unsigned k = key_of(xs[i], ms[i], tf);
            if ((k >> 10) == pre) atomicAdd(&sh[k & 1023u], 1u);
        }
        __syncthreads();
        if (t == 0) {
            unsigned run = 0u;
            for (unsigned b = 0; b < 1024u; b++) {
                if (r2 <= run + sh[b]) { sv[3] = (pre << 10) | b; break; }
                run += sh[b];
            }
        }
        __syncthreads();
        unsigned thr = sv[3];
        for (unsigned i = t; i < n; i += blockDim.x) {
            unsigned k = key_of(xs[i], ms[i], tf);
            out[i] = (k >= thr) ? xs[i] : 0.0f;
        }
        return;
    }

    unsigned b1 = sb1;
    unsigned r1 = sr1;
    unsigned k_lo = g_klo;
    unsigned fs   = g_fs;
    unsigned nlow = 1u << fs;                      // <= 4096
    unsigned b1start = k_lo + (b1 << fs);
    unsigned b1end   = b1start + (1u << fs);
    unsigned lowmask = nlow - 1u;
    unsigned cnt    = g_blk_cnt[blockIdx.x];
    unsigned region = blockIdx.x * PER_BLOCK;

    // ---- phase A: single region stream ----
    for (unsigned i = t; i < nlow; i += blockDim.x) sh[i] = 0u;
    __syncthreads();
    for (unsigned j = (unsigned)t; j < cnt; j += blockDim.x) {
        uint2 r = g_cand[region + j];
        if (r.x >= b1end) out[r.y] = xs[r.y];
        else if (r.x >= b1start) {
            agg_shared_add(sh, r.x & lowmask);
            unsigned pos = atomicAdd(&s_stash, 1u);
            if (pos < STASH_MAX) stash[pos] = r;
        }
    }
    __syncthreads();
    for (unsigned i = t; i < nlow; i += blockDim.x) {
        unsigned h = sh[i];
        if (h) atomicAdd(&g_lowh[i], h);
    }
    __threadfence();
    __syncthreads();
    if (t == 0) atomicAdd(&g_d2, 1u);

    // ---- block 0: exact threshold from low hist ----
    if (blockIdx.x == 0) {
        if (t == 0) { while (atomicAdd(&g_d2, 0u) < gridDim.x) {} }
        __syncthreads();
        unsigned q[16];
        unsigned loc = 0u;
        #pragma unroll
        for (int j = 0; j < 16; j++) { q[j] = g_lowh[t * 16 + j]; loc += q[j]; }
        ss[t] = loc;
        __syncthreads();
        for (int off = 1; off < NTHREADS; off <<= 1) {
            unsigned v = (t >= off) ? ss[t - off] : 0u;
            __syncthreads();
            ss[t] += v;
            __syncthreads();
        }
        unsigned inc3 = ss[t];
        unsigned bef3 = inc3 - loc;
        if (r1 > bef3 && r1 <= inc3) {
            unsigned run = bef3;
            #pragma unroll
            for (int j = 0; j < 16; j++) {
                if (r1 <= run + q[j]) {
                    g_thr_key = b1start + (unsigned)(t * 16 + j);
                    break;
                }
                run += q[j];
            }
        }
        __syncthreads();
        if (t == 0) { __threadfence(); atomicExch(&g_rdy2, 1u); }
    }

    // ---- apply thr to stashed b1 cands ----
    if (t == 0) { while (atomicAdd(&g_rdy2, 0u) == 0u) {} }
    __syncthreads();
    unsigned thr = g_thr_key;
    unsigned nst = s_stash;
    if (nst <= STASH_MAX) {
        for (unsigned j = (unsigned)t; j < nst; j += blockDim.x) {
            uint2 r = stash[j];
            if (r.x >= thr) out[r.y] = xs[r.y];
        }
    } else {
        for (unsigned j = (unsigned)t; j < cnt; j += blockDim.x) {
            uint2 r = g_cand[region + j];
            if (r.x >= thr && r.x < b1end) out[r.y] = xs[r.y];
        }
    }
}

// ---------------------------------------------------------------------------
extern "C" void kernel_launch(void* const* d_in, const int* in_sizes, int n_in,
                              void* d_out, int out_size) {
    const float* xs = (const float*)d_in[0];
    const float* ms = (const float*)d_in[1];
    const float* sp = (const float*)d_in[2];
    // d_in[3] = mask (unused by the reference computation)
    const int* t_ptr = (n_in >= 5) ? (const int*)d_in[4] : nullptr;

    unsigned n = (unsigned)in_sizes[0];
    float* out = (float*)d_out;

    zero_kernel<<<4, 1024>>>();
    sample_kernel<<<264, 256>>>(xs, ms, t_ptr, sp, n);
    passA_kernel<<<NBLOCKS, NTHREADS>>>(xs, ms, t_ptr, out, n);
    resolve_kernel<<<NBLOCKS, NTHREADS>>>(xs, ms, t_ptr, sp, out, n);
}